// round 1
// baseline (speedup 1.0000x reference)
#include <cuda_runtime.h>
#include <cuda_bf16.h>
#include <math.h>
#include <stdint.h>

// ---------------------------------------------------------------------------
// Problem constants (fixed shapes from reference)
// ---------------------------------------------------------------------------
#define N_NODES 20000
#define N_EDGES 320000
#define TOT_E   (N_EDGES + N_NODES)   // edges + self loops = 340000
#define N_GRAPHS 128
#define NEG_SLOPE 0.2f
#define EPS_F 1e-16f

#define HC1 320   // H=5, C=64
#define HC2 480   // H=5, C=96
#define HC3 32    // H=1, C=32

// ---------------------------------------------------------------------------
// Device scratch (static allocation — allowed)
// ---------------------------------------------------------------------------
__device__ float g_h1[N_NODES * HC1];
__device__ float g_o1[N_NODES * HC1];
__device__ float g_h2[N_NODES * HC2];
__device__ float g_o2[N_NODES * HC2];
__device__ float g_h3[N_NODES * HC3];
__device__ float g_o3[N_NODES * HC3];
__device__ float g_asrc[N_NODES * 5];
__device__ float g_adst[N_NODES * 5];
__device__ int   g_cnt[N_NODES];
__device__ int   g_rowptr[N_NODES + 1];
__device__ int   g_cursor[N_NODES];
__device__ int   g_csrc[TOT_E];
__device__ float g_pool[N_GRAPHS * 32];

// ---------------------------------------------------------------------------
// CSR construction
// ---------------------------------------------------------------------------
__global__ void init_kernel() {
    int i = blockIdx.x * blockDim.x + threadIdx.x;
    if (i < N_NODES) g_cnt[i] = 1;                 // self loop pre-counted
    if (i < N_GRAPHS * 32) g_pool[i] = 0.f;
}

__global__ void count_kernel(const int* __restrict__ ei) {
    int i = blockIdx.x * blockDim.x + threadIdx.x;
    if (i < N_EDGES) {
        int dst = ei[N_EDGES + i];
        atomicAdd(&g_cnt[dst], 1);
    }
}

// single-block inclusive scan over g_cnt -> g_rowptr (exclusive form)
__global__ void scan_kernel() {
    __shared__ int sh[1024];
    __shared__ int carry;
    int tid = threadIdx.x;
    if (tid == 0) { carry = 0; g_rowptr[0] = 0; }
    __syncthreads();
    for (int base = 0; base < N_NODES; base += 1024) {
        int i = base + tid;
        int v = (i < N_NODES) ? g_cnt[i] : 0;
        sh[tid] = v;
        __syncthreads();
        for (int off = 1; off < 1024; off <<= 1) {
            int t = (tid >= off) ? sh[tid - off] : 0;
            __syncthreads();
            sh[tid] += t;
            __syncthreads();
        }
        if (i < N_NODES) g_rowptr[i + 1] = sh[tid] + carry;
        __syncthreads();
        if (tid == 1023) carry += sh[1023];
        __syncthreads();
    }
}

__global__ void cursor_copy_kernel() {
    int i = blockIdx.x * blockDim.x + threadIdx.x;
    if (i < N_NODES) g_cursor[i] = g_rowptr[i];
}

__global__ void scatter_kernel(const int* __restrict__ ei) {
    int i = blockIdx.x * blockDim.x + threadIdx.x;
    if (i < N_EDGES) {
        int src = ei[i];
        int dst = ei[N_EDGES + i];
        int pos = atomicAdd(&g_cursor[dst], 1);
        g_csrc[pos] = src;
    }
}

__global__ void selfloop_kernel() {
    int v = blockIdx.x * blockDim.x + threadIdx.x;
    if (v < N_NODES) {
        int pos = atomicAdd(&g_cursor[v], 1);
        g_csrc[pos] = v;
    }
}

// ---------------------------------------------------------------------------
// SGEMM: C[N,M] = A[N,K] * B[M,K]^T  (B row-major [M,K])
// ---------------------------------------------------------------------------
__global__ void sgemm_nt(const float* __restrict__ A, const float* __restrict__ B,
                         float* __restrict__ C, int N, int M, int K) {
    const int BM = 64, BN = 64, BK = 16, TM = 4, TN = 4;
    __shared__ float As[BK][BM + 1];
    __shared__ float Bs[BK][BN + 1];
    int tid = threadIdx.x;                 // 256 threads
    int blockRow = blockIdx.y * BM;
    int blockCol = blockIdx.x * BN;
    int tr = (tid / (BN / TN)) * TM;       // 0..60
    int tc = (tid % (BN / TN)) * TN;       // 0..60
    float acc[TM][TN];
#pragma unroll
    for (int i = 0; i < TM; i++)
#pragma unroll
        for (int j = 0; j < TN; j++) acc[i][j] = 0.f;

    for (int k0 = 0; k0 < K; k0 += BK) {
#pragma unroll
        for (int l = 0; l < 4; l++) {
            int li = tid + l * 256;        // over BM*BK = 1024
            int r = li / BK, c = li % BK;
            int gr = blockRow + r, gc = k0 + c;
            As[c][r] = (gr < N && gc < K) ? A[(size_t)gr * K + gc] : 0.f;
            int br = blockCol + r;
            Bs[c][r] = (br < M && gc < K) ? B[(size_t)br * K + gc] : 0.f;
        }
        __syncthreads();
#pragma unroll
        for (int k = 0; k < BK; k++) {
            float a[TM], b[TN];
#pragma unroll
            for (int i = 0; i < TM; i++) a[i] = As[k][tr + i];
#pragma unroll
            for (int j = 0; j < TN; j++) b[j] = Bs[k][tc + j];
#pragma unroll
            for (int i = 0; i < TM; i++)
#pragma unroll
                for (int j = 0; j < TN; j++) acc[i][j] += a[i] * b[j];
        }
        __syncthreads();
    }
#pragma unroll
    for (int i = 0; i < TM; i++) {
        int gr = blockRow + tr + i;
        if (gr >= N) continue;
#pragma unroll
        for (int j = 0; j < TN; j++) {
            int gc = blockCol + tc + j;
            if (gc < M) C[(size_t)gr * M + gc] = acc[i][j];
        }
    }
}

// ---------------------------------------------------------------------------
// attention scores: asrc[n,h] = sum_c h[n,h,c]*att_src[h,c] (same for adst)
// one warp per (n,h)
// ---------------------------------------------------------------------------
__global__ void att_scores(const float* __restrict__ h,
                           const float* __restrict__ att_src,
                           const float* __restrict__ att_dst,
                           float* __restrict__ asrc, float* __restrict__ adst,
                           int N, int H, int C) {
    int warp = (blockIdx.x * blockDim.x + threadIdx.x) >> 5;
    int lane = threadIdx.x & 31;
    if (warp >= N * H) return;
    int n = warp / H, hh = warp % H;
    const float* hp = h + (size_t)n * H * C + hh * C;
    float s = 0.f, d = 0.f;
    for (int c = lane; c < C; c += 32) {
        float v = hp[c];
        s += v * att_src[hh * C + c];
        d += v * att_dst[hh * C + c];
    }
#pragma unroll
    for (int o = 16; o > 0; o >>= 1) {
        s += __shfl_down_sync(0xffffffffu, s, o);
        d += __shfl_down_sync(0xffffffffu, d, o);
    }
    if (lane == 0) { asrc[n * H + hh] = s; adst[n * H + hh] = d; }
}

// ---------------------------------------------------------------------------
// GAT aggregation: one block per destination node.
// out[v, h*C+c] = relu( sum_e alpha[e,h] * hfeat[src_e, h*C+c] + bias[h*C+c] )
// ---------------------------------------------------------------------------
__global__ void gat_agg(const float* __restrict__ hfeat,
                        const float* __restrict__ asrc,
                        const float* __restrict__ adst,
                        const float* __restrict__ bias,
                        float* __restrict__ out,
                        int H, int C) {
    const int CH = 128;                       // edge chunk
    int v = blockIdx.x;
    int HC = H * C;
    int tid = threadIdx.x;                    // 256 threads
    __shared__ float s_m[8], s_z[8];
    __shared__ int   s_src[CH];
    __shared__ float s_w[CH * 5];

    int base = g_rowptr[v];
    int deg = g_rowptr[v + 1] - base;

    if (tid < H) {
        float ad = adst[v * H + tid];
        float m = -INFINITY;
        for (int j = 0; j < deg; j++) {
            int s = g_csrc[base + j];
            float e = asrc[s * H + tid] + ad;
            e = (e > 0.f) ? e : NEG_SLOPE * e;
            m = fmaxf(m, e);
        }
        float z = 0.f;
        for (int j = 0; j < deg; j++) {
            int s = g_csrc[base + j];
            float e = asrc[s * H + tid] + ad;
            e = (e > 0.f) ? e : NEG_SLOPE * e;
            z += __expf(e - m);
        }
        s_m[tid] = m;
        s_z[tid] = z + EPS_F;
    }
    __syncthreads();

    float acc0 = 0.f, acc1 = 0.f;
    int c0 = tid;
    int c1 = tid + 256;
    int head0 = (c0 < HC) ? (c0 / C) : 0;
    int head1 = (c1 < HC) ? (c1 / C) : 0;

    for (int j0 = 0; j0 < deg; j0 += CH) {
        int ch = min(CH, deg - j0);
        for (int idx = tid; idx < ch * H; idx += 256) {
            int j = idx / H, hh = idx % H;
            int s = g_csrc[base + j0 + j];
            if (hh == 0) s_src[j] = s;
            float e = asrc[s * H + hh] + adst[v * H + hh];
            e = (e > 0.f) ? e : NEG_SLOPE * e;
            s_w[j * H + hh] = __expf(e - s_m[hh]) / s_z[hh];
        }
        __syncthreads();
        for (int j = 0; j < ch; j++) {
            const float* hp = hfeat + (size_t)s_src[j] * HC;
            float w0 = s_w[j * H + head0];
            float w1 = s_w[j * H + head1];
            if (c0 < HC) acc0 += w0 * hp[c0];
            if (c1 < HC) acc1 += w1 * hp[c1];
        }
        __syncthreads();
    }

    if (c0 < HC) out[(size_t)v * HC + c0] = fmaxf(acc0 + bias[c0], 0.f);
    if (c1 < HC) out[(size_t)v * HC + c1] = fmaxf(acc1 + bias[c1], 0.f);
}

// ---------------------------------------------------------------------------
// global add pool + MLP head
// ---------------------------------------------------------------------------
__global__ void pool_kernel(const int* __restrict__ batch) {
    int i = blockIdx.x * blockDim.x + threadIdx.x;
    if (i >= N_NODES * 32) return;
    int n = i / 32, c = i % 32;
    atomicAdd(&g_pool[batch[n] * 32 + c], g_o3[i]);
}

__global__ void mlp_kernel(const float* __restrict__ lin_w,
                           const float* __restrict__ lin_b,
                           const float* __restrict__ lin2_w,
                           const float* __restrict__ lin2_b,
                           float* __restrict__ out) {
    int g = blockIdx.x;
    __shared__ float sg[32];
    __shared__ float sred[256];
    int tid = threadIdx.x;
    if (tid < 32) sg[tid] = g_pool[g * 32 + tid];
    __syncthreads();
    float partial = 0.f;
    for (int u = tid; u < 1024; u += 256) {
        float d = lin_b[u];
        const float* wr = lin_w + u * 32;
#pragma unroll
        for (int c = 0; c < 32; c++) d += sg[c] * wr[c];
        d = fmaxf(d, 0.f);
        partial += d * lin2_w[u];
    }
    sred[tid] = partial;
    __syncthreads();
    for (int s = 128; s > 0; s >>= 1) {
        if (tid < s) sred[tid] += sred[tid + s];
        __syncthreads();
    }
    if (tid == 0) {
        float v = sred[0] + lin2_b[0];
        out[g] = 1.f / (1.f + __expf(-v));
    }
}

// ---------------------------------------------------------------------------
// launch
// ---------------------------------------------------------------------------
extern "C" void kernel_launch(void* const* d_in, const int* in_sizes, int n_in,
                              void* d_out, int out_size) {
    const float* x        = (const float*)d_in[0];
    const float* W1       = (const float*)d_in[1];
    const float* att_s1   = (const float*)d_in[2];
    const float* att_d1   = (const float*)d_in[3];
    const float* b1       = (const float*)d_in[4];
    const float* W2       = (const float*)d_in[5];
    const float* att_s2   = (const float*)d_in[6];
    const float* att_d2   = (const float*)d_in[7];
    const float* b2       = (const float*)d_in[8];
    const float* W3       = (const float*)d_in[9];
    const float* att_s3   = (const float*)d_in[10];
    const float* att_d3   = (const float*)d_in[11];
    const float* b3       = (const float*)d_in[12];
    const float* lin_w    = (const float*)d_in[13];
    const float* lin_b    = (const float*)d_in[14];
    const float* lin2_w   = (const float*)d_in[15];
    const float* lin2_b   = (const float*)d_in[16];
    const int*   ei       = (const int*)d_in[17];   // [2, E] int32
    const int*   batch    = (const int*)d_in[18];
    float* out = (float*)d_out;

    float *h1, *o1, *h2, *o2, *h3, *o3, *asrc, *adst;
    cudaGetSymbolAddress((void**)&h1, g_h1);
    cudaGetSymbolAddress((void**)&o1, g_o1);
    cudaGetSymbolAddress((void**)&h2, g_h2);
    cudaGetSymbolAddress((void**)&o2, g_o2);
    cudaGetSymbolAddress((void**)&h3, g_h3);
    cudaGetSymbolAddress((void**)&o3, g_o3);
    cudaGetSymbolAddress((void**)&asrc, g_asrc);
    cudaGetSymbolAddress((void**)&adst, g_adst);

    // ---- CSR build ----
    init_kernel<<<(N_NODES + 255) / 256, 256>>>();
    count_kernel<<<(N_EDGES + 255) / 256, 256>>>(ei);
    scan_kernel<<<1, 1024>>>();
    cursor_copy_kernel<<<(N_NODES + 255) / 256, 256>>>();
    scatter_kernel<<<(N_EDGES + 255) / 256, 256>>>(ei);
    selfloop_kernel<<<(N_NODES + 255) / 256, 256>>>();

    // ---- Layer 1: in 64 -> H=5, C=64 ----
    {
        dim3 grid((HC1 + 63) / 64, (N_NODES + 63) / 64);
        sgemm_nt<<<grid, 256>>>(x, W1, h1, N_NODES, HC1, 64);
        int warps = N_NODES * 5;
        att_scores<<<(warps * 32 + 127) / 128, 128>>>(h1, att_s1, att_d1, asrc, adst, N_NODES, 5, 64);
        gat_agg<<<N_NODES, 256>>>(h1, asrc, adst, b1, o1, 5, 64);
    }
    // ---- Layer 2: 320 -> H=5, C=96 ----
    {
        dim3 grid((HC2 + 63) / 64, (N_NODES + 63) / 64);
        sgemm_nt<<<grid, 256>>>(o1, W2, h2, N_NODES, HC2, HC1);
        int warps = N_NODES * 5;
        att_scores<<<(warps * 32 + 127) / 128, 128>>>(h2, att_s2, att_d2, asrc, adst, N_NODES, 5, 96);
        gat_agg<<<N_NODES, 256>>>(h2, asrc, adst, b2, o2, 5, 96);
    }
    // ---- Layer 3: 480 -> H=1, C=32 ----
    {
        dim3 grid((HC3 + 63) / 64, (N_NODES + 63) / 64);
        sgemm_nt<<<grid, 256>>>(o2, W3, h3, N_NODES, HC3, HC2);
        int warps = N_NODES * 1;
        att_scores<<<(warps * 32 + 127) / 128, 128>>>(h3, att_s3, att_d3, asrc, adst, N_NODES, 1, 32);
        gat_agg<<<N_NODES, 256>>>(h3, asrc, adst, b3, o3, 1, 32);
    }

    // ---- pool + MLP ----
    pool_kernel<<<(N_NODES * 32 + 255) / 256, 256>>>(batch);
    mlp_kernel<<<N_GRAPHS, 256>>>(lin_w, lin_b, lin2_w, lin2_b, out);
}

// round 2
// speedup vs baseline: 1.4539x; 1.4539x over previous
#include <cuda_runtime.h>
#include <cuda_bf16.h>
#include <math.h>
#include <stdint.h>

// ---------------------------------------------------------------------------
// Problem constants
// ---------------------------------------------------------------------------
#define N_NODES 20000
#define N_EDGES 320000
#define TOT_E   (N_EDGES + N_NODES)
#define N_GRAPHS 128
#define NEG_SLOPE 0.2f
#define EPS_F 1e-16f

#define HC1 320   // H=5, C=64
#define HC2 480   // H=5, C=96
#define HC3 32    // H=1, C=32

// ---------------------------------------------------------------------------
// Device scratch
// ---------------------------------------------------------------------------
__device__ __align__(16) float g_h1[N_NODES * HC1];
__device__ __align__(16) float g_o1[N_NODES * HC1];
__device__ __align__(16) float g_h2[N_NODES * HC2];
__device__ __align__(16) float g_o2[N_NODES * HC2];
__device__ __align__(16) float g_h3[N_NODES * HC3];
__device__ __align__(16) float g_o3[N_NODES * HC3];
__device__ float g_asrc[N_NODES * 5];
__device__ float g_adst[N_NODES * 5];
__device__ int   g_cnt[N_NODES];
__device__ int   g_rowptr[N_NODES + 1];
__device__ int   g_cursor[N_NODES];
__device__ int   g_csrc[TOT_E];
__device__ float g_pool[N_GRAPHS * 32];

// ---------------------------------------------------------------------------
// CSR construction
// ---------------------------------------------------------------------------
__global__ void init_kernel() {
    int i = blockIdx.x * blockDim.x + threadIdx.x;
    if (i < N_NODES) g_cnt[i] = 1;
    if (i < N_GRAPHS * 32) g_pool[i] = 0.f;
}

__global__ void count_kernel(const int* __restrict__ ei) {
    int i = blockIdx.x * blockDim.x + threadIdx.x;
    if (i < N_EDGES) atomicAdd(&g_cnt[ei[N_EDGES + i]], 1);
}

__global__ void scan_kernel() {
    __shared__ int sh[1024];
    __shared__ int carry;
    int tid = threadIdx.x;
    if (tid == 0) { carry = 0; g_rowptr[0] = 0; }
    __syncthreads();
    for (int base = 0; base < N_NODES; base += 1024) {
        int i = base + tid;
        int v = (i < N_NODES) ? g_cnt[i] : 0;
        sh[tid] = v;
        __syncthreads();
        for (int off = 1; off < 1024; off <<= 1) {
            int t = (tid >= off) ? sh[tid - off] : 0;
            __syncthreads();
            sh[tid] += t;
            __syncthreads();
        }
        if (i < N_NODES) g_rowptr[i + 1] = sh[tid] + carry;
        __syncthreads();
        if (tid == 1023) carry += sh[1023];
        __syncthreads();
    }
}

__global__ void cursor_copy_kernel() {
    int i = blockIdx.x * blockDim.x + threadIdx.x;
    if (i < N_NODES) g_cursor[i] = g_rowptr[i];
}

__global__ void scatter_kernel(const int* __restrict__ ei) {
    int i = blockIdx.x * blockDim.x + threadIdx.x;
    if (i < N_EDGES) {
        int src = ei[i];
        int dst = ei[N_EDGES + i];
        int pos = atomicAdd(&g_cursor[dst], 1);
        g_csrc[pos] = src;
    }
}

__global__ void selfloop_kernel() {
    int v = blockIdx.x * blockDim.x + threadIdx.x;
    if (v < N_NODES) {
        int pos = atomicAdd(&g_cursor[v], 1);
        g_csrc[pos] = v;
    }
}

// ---------------------------------------------------------------------------
// tf32 tensor-core GEMM: C[N,M] = A[N,K] * B[M,K]^T
// BM=128, BN=64, BK=16, 256 threads = 8 warps (4 M x 2 N), 32x32 per warp.
// K must be a multiple of 16 (true: 64, 320, 480).
// ---------------------------------------------------------------------------
__device__ __forceinline__ uint32_t f2tf32(float f) {
    uint32_t u;
    asm("cvt.rna.tf32.f32 %0, %1;" : "=r"(u) : "f"(f));
    return u;
}

__global__ void __launch_bounds__(256, 2)
gemm_tf32(const float* __restrict__ A, const float* __restrict__ B,
          float* __restrict__ C, int N, int M, int K) {
    const int BM = 128, BN = 64, BK = 16;
    __shared__ float As[BM][BK + 4];
    __shared__ float Bs[BN][BK + 4];

    int tid  = threadIdx.x;
    int lane = tid & 31;
    int wid  = tid >> 5;
    int warpM = wid & 3;            // 0..3
    int warpN = wid >> 2;           // 0..1
    int wr = warpM * 32;            // warp row base inside tile
    int wc = warpN * 32;            // warp col base inside tile
    int gid = lane >> 2;            // 0..7
    int tig = lane & 3;             // 0..3

    int blockRow = blockIdx.y * BM;
    int blockCol = blockIdx.x * BN;

    float acc[2][4][4];
#pragma unroll
    for (int mt = 0; mt < 2; mt++)
#pragma unroll
        for (int nt = 0; nt < 4; nt++)
#pragma unroll
            for (int i = 0; i < 4; i++) acc[mt][nt][i] = 0.f;

    for (int k0 = 0; k0 < K; k0 += BK) {
        // load A: 128x16 = 512 float4, 2 per thread
#pragma unroll
        for (int l = 0; l < 2; l++) {
            int idx = tid + l * 256;
            int r = idx >> 2, c = (idx & 3) << 2;
            float4 v = make_float4(0.f, 0.f, 0.f, 0.f);
            if (blockRow + r < N)
                v = *(const float4*)(A + (size_t)(blockRow + r) * K + k0 + c);
            As[r][c] = v.x; As[r][c+1] = v.y; As[r][c+2] = v.z; As[r][c+3] = v.w;
        }
        // load B: 64x16 = 256 float4, 1 per thread
        {
            int r = tid >> 2, c = (tid & 3) << 2;
            float4 v = make_float4(0.f, 0.f, 0.f, 0.f);
            if (blockCol + r < M)
                v = *(const float4*)(B + (size_t)(blockCol + r) * K + k0 + c);
            Bs[r][c] = v.x; Bs[r][c+1] = v.y; Bs[r][c+2] = v.z; Bs[r][c+3] = v.w;
        }
        __syncthreads();

#pragma unroll
        for (int kk = 0; kk < 2; kk++) {
            int kb = kk * 8;
            uint32_t a[2][4], b[4][2];
#pragma unroll
            for (int mt = 0; mt < 2; mt++) {
                int r0 = wr + mt * 16;
                a[mt][0] = f2tf32(As[r0 + gid    ][kb + tig    ]);
                a[mt][1] = f2tf32(As[r0 + gid + 8][kb + tig    ]);
                a[mt][2] = f2tf32(As[r0 + gid    ][kb + tig + 4]);
                a[mt][3] = f2tf32(As[r0 + gid + 8][kb + tig + 4]);
            }
#pragma unroll
            for (int nt = 0; nt < 4; nt++) {
                int n0 = wc + nt * 8 + gid;
                b[nt][0] = f2tf32(Bs[n0][kb + tig    ]);
                b[nt][1] = f2tf32(Bs[n0][kb + tig + 4]);
            }
#pragma unroll
            for (int mt = 0; mt < 2; mt++)
#pragma unroll
                for (int nt = 0; nt < 4; nt++) {
                    asm volatile(
                        "mma.sync.aligned.m16n8k8.row.col.f32.tf32.tf32.f32 "
                        "{%0,%1,%2,%3}, {%4,%5,%6,%7}, {%8,%9}, {%0,%1,%2,%3};"
                        : "+f"(acc[mt][nt][0]), "+f"(acc[mt][nt][1]),
                          "+f"(acc[mt][nt][2]), "+f"(acc[mt][nt][3])
                        : "r"(a[mt][0]), "r"(a[mt][1]), "r"(a[mt][2]), "r"(a[mt][3]),
                          "r"(b[nt][0]), "r"(b[nt][1]));
                }
        }
        __syncthreads();
    }

    // epilogue: c0: (gid, tig*2) c1: +1 col, c2: row+8, c3
#pragma unroll
    for (int mt = 0; mt < 2; mt++) {
#pragma unroll
        for (int nt = 0; nt < 4; nt++) {
            int r0 = blockRow + wr + mt * 16 + gid;
            int c0 = blockCol + wc + nt * 8 + tig * 2;
            if (r0 < N && c0 + 1 < M) {
                C[(size_t)r0 * M + c0]     = acc[mt][nt][0];
                C[(size_t)r0 * M + c0 + 1] = acc[mt][nt][1];
            }
            if (r0 + 8 < N && c0 + 1 < M) {
                C[(size_t)(r0 + 8) * M + c0]     = acc[mt][nt][2];
                C[(size_t)(r0 + 8) * M + c0 + 1] = acc[mt][nt][3];
            }
        }
    }
}

// ---------------------------------------------------------------------------
// attention scores
// ---------------------------------------------------------------------------
__global__ void att_scores(const float* __restrict__ h,
                           const float* __restrict__ att_src,
                           const float* __restrict__ att_dst,
                           float* __restrict__ asrc, float* __restrict__ adst,
                           int N, int H, int C) {
    int warp = (blockIdx.x * blockDim.x + threadIdx.x) >> 5;
    int lane = threadIdx.x & 31;
    if (warp >= N * H) return;
    int n = warp / H, hh = warp % H;
    const float* hp = h + (size_t)n * H * C + hh * C;
    float s = 0.f, d = 0.f;
    for (int c = lane; c < C; c += 32) {
        float v = hp[c];
        s += v * att_src[hh * C + c];
        d += v * att_dst[hh * C + c];
    }
#pragma unroll
    for (int o = 16; o > 0; o >>= 1) {
        s += __shfl_down_sync(0xffffffffu, s, o);
        d += __shfl_down_sync(0xffffffffu, d, o);
    }
    if (lane == 0) { asrc[n * H + hh] = s; adst[n * H + hh] = d; }
}

// ---------------------------------------------------------------------------
// GAT aggregation: one block per dst node; warp-parallel softmax.
// ---------------------------------------------------------------------------
__global__ void gat_agg(const float* __restrict__ hfeat,
                        const float* __restrict__ asrc,
                        const float* __restrict__ adst,
                        const float* __restrict__ bias,
                        float* __restrict__ out,
                        int H, int C) {
    const int CH = 128;
    int v = blockIdx.x;
    int HC = H * C;
    int tid = threadIdx.x, lane = tid & 31, wid = tid >> 5;
    __shared__ float s_m[8], s_iz[8], s_ad[8];
    __shared__ int   s_src[CH];
    __shared__ float s_w[CH * 5];

    int base = g_rowptr[v];
    int deg = g_rowptr[v + 1] - base;

    if (tid < H) s_ad[tid] = adst[v * H + tid];
    __syncthreads();

    // warp-parallel softmax normalizers: warp h handles head h
    if (wid < H) {
        int h = wid;
        float ad = s_ad[h];
        float m = -INFINITY;
        for (int j = lane; j < deg; j += 32) {
            int s = g_csrc[base + j];
            float e = asrc[s * H + h] + ad;
            e = (e > 0.f) ? e : NEG_SLOPE * e;
            m = fmaxf(m, e);
        }
#pragma unroll
        for (int o = 16; o > 0; o >>= 1)
            m = fmaxf(m, __shfl_xor_sync(0xffffffffu, m, o));
        float z = 0.f;
        for (int j = lane; j < deg; j += 32) {
            int s = g_csrc[base + j];
            float e = asrc[s * H + h] + ad;
            e = (e > 0.f) ? e : NEG_SLOPE * e;
            z += __expf(e - m);
        }
#pragma unroll
        for (int o = 16; o > 0; o >>= 1)
            z += __shfl_xor_sync(0xffffffffu, z, o);
        if (lane == 0) { s_m[h] = m; s_iz[h] = 1.f / (z + EPS_F); }
    }
    __syncthreads();

    float acc0 = 0.f, acc1 = 0.f;
    int c0 = tid;
    int c1 = tid + 256;
    int head0 = (c0 < HC) ? (c0 / C) : 0;
    int head1 = (c1 < HC) ? (c1 / C) : 0;

    for (int j0 = 0; j0 < deg; j0 += CH) {
        int ch = min(CH, deg - j0);
        for (int idx = tid; idx < ch * H; idx += blockDim.x) {
            int j = idx / H, hh = idx % H;
            int s = g_csrc[base + j0 + j];
            if (hh == 0) s_src[j] = s;
            float e = asrc[s * H + hh] + s_ad[hh];
            e = (e > 0.f) ? e : NEG_SLOPE * e;
            s_w[j * H + hh] = __expf(e - s_m[hh]) * s_iz[hh];
        }
        __syncthreads();
        for (int j = 0; j < ch; j++) {
            const float* hp = hfeat + (size_t)s_src[j] * HC;
            float w0 = s_w[j * H + head0];
            float w1 = s_w[j * H + head1];
            if (c0 < HC) acc0 += w0 * hp[c0];
            if (c1 < HC) acc1 += w1 * hp[c1];
        }
        __syncthreads();
    }

    if (c0 < HC) out[(size_t)v * HC + c0] = fmaxf(acc0 + bias[c0], 0.f);
    if (c1 < HC) out[(size_t)v * HC + c1] = fmaxf(acc1 + bias[c1], 0.f);
}

// ---------------------------------------------------------------------------
// global add pool + MLP head
// ---------------------------------------------------------------------------
__global__ void pool_kernel(const int* __restrict__ batch) {
    int i = blockIdx.x * blockDim.x + threadIdx.x;
    if (i >= N_NODES * 32) return;
    int n = i / 32, c = i % 32;
    atomicAdd(&g_pool[batch[n] * 32 + c], g_o3[i]);
}

__global__ void mlp_kernel(const float* __restrict__ lin_w,
                           const float* __restrict__ lin_b,
                           const float* __restrict__ lin2_w,
                           const float* __restrict__ lin2_b,
                           float* __restrict__ out) {
    int g = blockIdx.x;
    __shared__ float sg[32];
    __shared__ float sred[256];
    int tid = threadIdx.x;
    if (tid < 32) sg[tid] = g_pool[g * 32 + tid];
    __syncthreads();
    float partial = 0.f;
    for (int u = tid; u < 1024; u += 256) {
        float d = lin_b[u];
        const float* wr = lin_w + u * 32;
#pragma unroll
        for (int c = 0; c < 32; c++) d += sg[c] * wr[c];
        d = fmaxf(d, 0.f);
        partial += d * lin2_w[u];
    }
    sred[tid] = partial;
    __syncthreads();
    for (int s = 128; s > 0; s >>= 1) {
        if (tid < s) sred[tid] += sred[tid + s];
        __syncthreads();
    }
    if (tid == 0) {
        float v = sred[0] + lin2_b[0];
        out[g] = 1.f / (1.f + __expf(-v));
    }
}

// ---------------------------------------------------------------------------
// launch
// ---------------------------------------------------------------------------
extern "C" void kernel_launch(void* const* d_in, const int* in_sizes, int n_in,
                              void* d_out, int out_size) {
    const float* x        = (const float*)d_in[0];
    const float* W1       = (const float*)d_in[1];
    const float* att_s1   = (const float*)d_in[2];
    const float* att_d1   = (const float*)d_in[3];
    const float* b1       = (const float*)d_in[4];
    const float* W2       = (const float*)d_in[5];
    const float* att_s2   = (const float*)d_in[6];
    const float* att_d2   = (const float*)d_in[7];
    const float* b2       = (const float*)d_in[8];
    const float* W3       = (const float*)d_in[9];
    const float* att_s3   = (const float*)d_in[10];
    const float* att_d3   = (const float*)d_in[11];
    const float* b3       = (const float*)d_in[12];
    const float* lin_w    = (const float*)d_in[13];
    const float* lin_b    = (const float*)d_in[14];
    const float* lin2_w   = (const float*)d_in[15];
    const float* lin2_b   = (const float*)d_in[16];
    const int*   ei       = (const int*)d_in[17];
    const int*   batch    = (const int*)d_in[18];
    float* out = (float*)d_out;

    float *h1, *o1, *h2, *o2, *h3, *o3, *asrc, *adst;
    cudaGetSymbolAddress((void**)&h1, g_h1);
    cudaGetSymbolAddress((void**)&o1, g_o1);
    cudaGetSymbolAddress((void**)&h2, g_h2);
    cudaGetSymbolAddress((void**)&o2, g_o2);
    cudaGetSymbolAddress((void**)&h3, g_h3);
    cudaGetSymbolAddress((void**)&o3, g_o3);
    cudaGetSymbolAddress((void**)&asrc, g_asrc);
    cudaGetSymbolAddress((void**)&adst, g_adst);

    // ---- CSR build ----
    init_kernel<<<(N_NODES + 255) / 256, 256>>>();
    count_kernel<<<(N_EDGES + 255) / 256, 256>>>(ei);
    scan_kernel<<<1, 1024>>>();
    cursor_copy_kernel<<<(N_NODES + 255) / 256, 256>>>();
    scatter_kernel<<<(N_EDGES + 255) / 256, 256>>>(ei);
    selfloop_kernel<<<(N_NODES + 255) / 256, 256>>>();

    const int GY = (N_NODES + 127) / 128;

    // ---- Layer 1: 64 -> H=5, C=64 ----
    {
        dim3 grid((HC1 + 63) / 64, GY);
        gemm_tf32<<<grid, 256>>>(x, W1, h1, N_NODES, HC1, 64);
        int warps = N_NODES * 5;
        att_scores<<<(warps * 32 + 127) / 128, 128>>>(h1, att_s1, att_d1, asrc, adst, N_NODES, 5, 64);
        gat_agg<<<N_NODES, 256>>>(h1, asrc, adst, b1, o1, 5, 64);
    }
    // ---- Layer 2: 320 -> H=5, C=96 ----
    {
        dim3 grid((HC2 + 63) / 64, GY);
        gemm_tf32<<<grid, 256>>>(o1, W2, h2, N_NODES, HC2, HC1);
        int warps = N_NODES * 5;
        att_scores<<<(warps * 32 + 127) / 128, 128>>>(h2, att_s2, att_d2, asrc, adst, N_NODES, 5, 96);
        gat_agg<<<N_NODES, 256>>>(h2, asrc, adst, b2, o2, 5, 96);
    }
    // ---- Layer 3: 480 -> H=1, C=32 ----
    {
        dim3 grid((HC3 + 63) / 64, GY);
        gemm_tf32<<<grid, 256>>>(o2, W3, h3, N_NODES, HC3, HC2);
        int warps = N_NODES * 1;
        att_scores<<<(warps * 32 + 127) / 128, 128>>>(h3, att_s3, att_d3, asrc, adst, N_NODES, 1, 32);
        gat_agg<<<N_NODES, 256>>>(h3, asrc, adst, b3, o3, 1, 32);
    }

    // ---- pool + MLP ----
    pool_kernel<<<(N_NODES * 32 + 255) / 256, 256>>>(batch);
    mlp_kernel<<<N_GRAPHS, 256>>>(lin_w, lin_b, lin2_w, lin2_b, out);
}

// round 3
// speedup vs baseline: 2.1446x; 1.4751x over previous
#include <cuda_runtime.h>
#include <cuda_bf16.h>
#include <math.h>
#include <stdint.h>

// ---------------------------------------------------------------------------
// Problem constants
// ---------------------------------------------------------------------------
#define N_NODES 20000
#define N_EDGES 320000
#define TOT_E   (N_EDGES + N_NODES)
#define N_GRAPHS 128
#define NEG_SLOPE 0.2f
#define EPS_F 1e-16f

#define HC1 320   // H=5, C=64
#define HC2 480   // H=5, C=96
#define HC3 32    // H=1, C=32

#define N_BLK ((N_NODES + 255) / 256)   // 79

// ---------------------------------------------------------------------------
// Device scratch
// ---------------------------------------------------------------------------
__device__ __align__(16) float g_h1[N_NODES * HC1];
__device__ __align__(16) float g_o1[N_NODES * HC1];
__device__ __align__(16) float g_h2[N_NODES * HC2];
__device__ __align__(16) float g_o2[N_NODES * HC2];
__device__ __align__(16) float g_h3[N_NODES * HC3];
__device__ __align__(16) float g_o3[N_NODES * HC3];
__device__ float g_asrc[N_NODES * 5];
__device__ float g_adst[N_NODES * 5];
__device__ int   g_cnt[N_NODES];
__device__ int   g_rowptr[N_NODES + 1];
__device__ int   g_cursor[N_NODES];
__device__ int   g_csrc[TOT_E];
__device__ int   g_bsum[N_BLK];
__device__ int   g_boff[N_BLK];
__device__ float g_pool[N_GRAPHS * 32];

// ---------------------------------------------------------------------------
// CSR construction
// ---------------------------------------------------------------------------
__global__ void init_kernel() {
    int i = blockIdx.x * blockDim.x + threadIdx.x;
    if (i < N_NODES) g_cnt[i] = 1;                 // self loop pre-counted
    if (i < N_GRAPHS * 32) g_pool[i] = 0.f;
}

__global__ void count_kernel(const int* __restrict__ ei) {
    int i = blockIdx.x * blockDim.x + threadIdx.x;
    if (i < N_EDGES) atomicAdd(&g_cnt[ei[N_EDGES + i]], 1);
}

// hierarchical scan: block-local inclusive
__global__ void scan1_kernel() {
    int i = blockIdx.x * 256 + threadIdx.x;
    int lane = threadIdx.x & 31, w = threadIdx.x >> 5;
    int x = (i < N_NODES) ? g_cnt[i] : 0;
#pragma unroll
    for (int o = 1; o < 32; o <<= 1) {
        int t = __shfl_up_sync(0xffffffffu, x, o);
        if (lane >= o) x += t;
    }
    __shared__ int wsum[8];
    if (lane == 31) wsum[w] = x;
    __syncthreads();
    if (w == 0) {
        int s = (lane < 8) ? wsum[lane] : 0;
#pragma unroll
        for (int o = 1; o < 8; o <<= 1) {
            int t = __shfl_up_sync(0xffffffffu, s, o);
            if (lane >= o) s += t;
        }
        if (lane < 8) wsum[lane] = s;
    }
    __syncthreads();
    int incl = x + ((w > 0) ? wsum[w - 1] : 0);
    if (i < N_NODES) g_rowptr[i + 1] = incl;       // block-local inclusive
    if (threadIdx.x == 255) g_bsum[blockIdx.x] = incl;
}

// scan block sums (exclusive) -> g_boff
__global__ void scan2_kernel() {
    int tid = threadIdx.x;                          // 128 threads, 1 block
    int lane = tid & 31, w = tid >> 5;
    int x = (tid < N_BLK) ? g_bsum[tid] : 0;
#pragma unroll
    for (int o = 1; o < 32; o <<= 1) {
        int t = __shfl_up_sync(0xffffffffu, x, o);
        if (lane >= o) x += t;
    }
    __shared__ int wsum[4];
    if (lane == 31) wsum[w] = x;
    __syncthreads();
    if (w == 0) {
        int s = (lane < 4) ? wsum[lane] : 0;
#pragma unroll
        for (int o = 1; o < 4; o <<= 1) {
            int t = __shfl_up_sync(0xffffffffu, s, o);
            if (lane >= o) s += t;
        }
        if (lane < 4) wsum[lane] = s;
    }
    __syncthreads();
    int incl = x + ((w > 0) ? wsum[w - 1] : 0);
    int excl = incl - ((tid < N_BLK) ? g_bsum[tid] : 0);
    if (tid < N_BLK) g_boff[tid] = excl;
}

// apply offsets; cursor[i] = global exclusive = incl - cnt[i]
__global__ void scan3_kernel() {
    int i = blockIdx.x * 256 + threadIdx.x;
    if (i == 0) g_rowptr[0] = 0;
    if (i < N_NODES) {
        int incl = g_rowptr[i + 1] + g_boff[blockIdx.x];
        g_rowptr[i + 1] = incl;
        g_cursor[i] = incl - g_cnt[i];
    }
}

// scatter edges + self loops in one pass
__global__ void scatter_kernel(const int* __restrict__ ei) {
    int i = blockIdx.x * blockDim.x + threadIdx.x;
    if (i >= TOT_E) return;
    int src, dst;
    if (i < N_EDGES) { src = ei[i]; dst = ei[N_EDGES + i]; }
    else             { src = dst = i - N_EDGES; }
    int pos = atomicAdd(&g_cursor[dst], 1);
    g_csrc[pos] = src;
}

// ---------------------------------------------------------------------------
// tf32 tensor-core GEMM: C[N,M] = A[N,K] * B[M,K]^T
// BM=128, BN=64, BK=16, 256 thr = 8 warps (4M x 2N), 32x32/warp.
// Double-buffered smem holding PRE-CONVERTED tf32 values.
// ---------------------------------------------------------------------------
__device__ __forceinline__ uint32_t f2tf32(float f) {
    uint32_t u;
    asm("cvt.rna.tf32.f32 %0, %1;" : "=r"(u) : "f"(f));
    return u;
}

__global__ void __launch_bounds__(256, 2)
gemm_tf32(const float* __restrict__ A, const float* __restrict__ B,
          float* __restrict__ C, int N, int M, int K) {
    const int BM = 128, BN = 64, BK = 16;
    __shared__ uint32_t As[2][BM][BK + 4];
    __shared__ uint32_t Bs[2][BN][BK + 4];

    int tid  = threadIdx.x;
    int lane = tid & 31;
    int wid  = tid >> 5;
    int warpM = wid & 3;
    int warpN = wid >> 2;
    int wr = warpM * 32;
    int wc = warpN * 32;
    int gid = lane >> 2;
    int tig = lane & 3;

    int blockRow = blockIdx.y * BM;
    int blockCol = blockIdx.x * BN;

    // load coords
    int ar0 = (tid) >> 2,        ac0 = (tid & 3) << 2;        // A part 0 (idx=tid)
    int ar1 = (tid + 256) >> 2,  ac1 = ac0;                   // A part 1 (idx=tid+256)
    int br  = tid >> 2,          bc  = (tid & 3) << 2;        // B

    float4 va0, va1, vb;
    const float4 zero4 = make_float4(0.f, 0.f, 0.f, 0.f);

    auto loadTile = [&](int k0) {
        va0 = (blockRow + ar0 < N) ? *(const float4*)(A + (size_t)(blockRow + ar0) * K + k0 + ac0) : zero4;
        va1 = (blockRow + ar1 < N) ? *(const float4*)(A + (size_t)(blockRow + ar1) * K + k0 + ac1) : zero4;
        vb  = (blockCol + br  < M) ? *(const float4*)(B + (size_t)(blockCol + br)  * K + k0 + bc)  : zero4;
    };
    auto storeTile = [&](int buf) {
        As[buf][ar0][ac0] = f2tf32(va0.x); As[buf][ar0][ac0+1] = f2tf32(va0.y);
        As[buf][ar0][ac0+2] = f2tf32(va0.z); As[buf][ar0][ac0+3] = f2tf32(va0.w);
        As[buf][ar1][ac1] = f2tf32(va1.x); As[buf][ar1][ac1+1] = f2tf32(va1.y);
        As[buf][ar1][ac1+2] = f2tf32(va1.z); As[buf][ar1][ac1+3] = f2tf32(va1.w);
        Bs[buf][br][bc] = f2tf32(vb.x); Bs[buf][br][bc+1] = f2tf32(vb.y);
        Bs[buf][br][bc+2] = f2tf32(vb.z); Bs[buf][br][bc+3] = f2tf32(vb.w);
    };

    float acc[2][4][4];
#pragma unroll
    for (int mt = 0; mt < 2; mt++)
#pragma unroll
        for (int nt = 0; nt < 4; nt++)
#pragma unroll
            for (int i = 0; i < 4; i++) acc[mt][nt][i] = 0.f;

    loadTile(0);
    storeTile(0);
    __syncthreads();

    int buf = 0;
    for (int k0 = BK; k0 <= K; k0 += BK) {
        bool has = (k0 < K);
        if (has) loadTile(k0);

        // compute on current buf
#pragma unroll
        for (int kk = 0; kk < 2; kk++) {
            int kb = kk * 8;
            uint32_t a[2][4], b[4][2];
#pragma unroll
            for (int mt = 0; mt < 2; mt++) {
                int r0 = wr + mt * 16;
                a[mt][0] = As[buf][r0 + gid    ][kb + tig    ];
                a[mt][1] = As[buf][r0 + gid + 8][kb + tig    ];
                a[mt][2] = As[buf][r0 + gid    ][kb + tig + 4];
                a[mt][3] = As[buf][r0 + gid + 8][kb + tig + 4];
            }
#pragma unroll
            for (int nt = 0; nt < 4; nt++) {
                int n0 = wc + nt * 8 + gid;
                b[nt][0] = Bs[buf][n0][kb + tig    ];
                b[nt][1] = Bs[buf][n0][kb + tig + 4];
            }
#pragma unroll
            for (int mt = 0; mt < 2; mt++)
#pragma unroll
                for (int nt = 0; nt < 4; nt++) {
                    asm volatile(
                        "mma.sync.aligned.m16n8k8.row.col.f32.tf32.tf32.f32 "
                        "{%0,%1,%2,%3}, {%4,%5,%6,%7}, {%8,%9}, {%0,%1,%2,%3};"
                        : "+f"(acc[mt][nt][0]), "+f"(acc[mt][nt][1]),
                          "+f"(acc[mt][nt][2]), "+f"(acc[mt][nt][3])
                        : "r"(a[mt][0]), "r"(a[mt][1]), "r"(a[mt][2]), "r"(a[mt][3]),
                          "r"(b[nt][0]), "r"(b[nt][1]));
                }
        }

        if (has) storeTile(buf ^ 1);
        __syncthreads();
        buf ^= 1;
    }

#pragma unroll
    for (int mt = 0; mt < 2; mt++) {
#pragma unroll
        for (int nt = 0; nt < 4; nt++) {
            int r0 = blockRow + wr + mt * 16 + gid;
            int c0 = blockCol + wc + nt * 8 + tig * 2;
            if (r0 < N && c0 + 1 < M + 1 && c0 < M) {
                C[(size_t)r0 * M + c0]     = acc[mt][nt][0];
                C[(size_t)r0 * M + c0 + 1] = acc[mt][nt][1];
            }
            if (r0 + 8 < N && c0 < M) {
                C[(size_t)(r0 + 8) * M + c0]     = acc[mt][nt][2];
                C[(size_t)(r0 + 8) * M + c0 + 1] = acc[mt][nt][3];
            }
        }
    }
}

// ---------------------------------------------------------------------------
// attention scores
// ---------------------------------------------------------------------------
__global__ void att_scores(const float* __restrict__ h,
                           const float* __restrict__ att_src,
                           const float* __restrict__ att_dst,
                           float* __restrict__ asrc, float* __restrict__ adst,
                           int N, int H, int C) {
    int warp = (blockIdx.x * blockDim.x + threadIdx.x) >> 5;
    int lane = threadIdx.x & 31;
    if (warp >= N * H) return;
    int n = warp / H, hh = warp % H;
    const float* hp = h + (size_t)n * H * C + hh * C;
    float s = 0.f, d = 0.f;
    for (int c = lane; c < C; c += 32) {
        float v = hp[c];
        s += v * att_src[hh * C + c];
        d += v * att_dst[hh * C + c];
    }
#pragma unroll
    for (int o = 16; o > 0; o >>= 1) {
        s += __shfl_down_sync(0xffffffffu, s, o);
        d += __shfl_down_sync(0xffffffffu, d, o);
    }
    if (lane == 0) { asrc[n * H + hh] = s; adst[n * H + hh] = d; }
}

// ---------------------------------------------------------------------------
// GAT aggregation, H=5, float4-vectorized channels. One block (192 thr) per node.
// ---------------------------------------------------------------------------
template<int C>
__global__ void __launch_bounds__(192)
gat_agg5(const float* __restrict__ hfeat,
         const float* __restrict__ asrc,
         const float* __restrict__ adst,
         const float* __restrict__ bias,
         float* __restrict__ out) {
    const int H = 5, HC = 5 * C, NC4 = HC / 4;
    const int CH = 64;
    __shared__ float s_m[5], s_iz[5], s_ad[5];
    __shared__ int   s_src[CH];
    __shared__ float s_w[CH * 5];

    int v = blockIdx.x;
    int tid = threadIdx.x, lane = tid & 31, wid = tid >> 5;
    int base = g_rowptr[v];
    int deg = g_rowptr[v + 1] - base;

    if (tid < 5) s_ad[tid] = adst[v * 5 + tid];
    __syncthreads();

    if (wid < 5) {
        int h = wid;
        float ad = s_ad[h];
        float m = -INFINITY;
        for (int j = lane; j < deg; j += 32) {
            int s = g_csrc[base + j];
            float e = asrc[s * 5 + h] + ad;
            e = (e > 0.f) ? e : NEG_SLOPE * e;
            m = fmaxf(m, e);
        }
#pragma unroll
        for (int o = 16; o > 0; o >>= 1)
            m = fmaxf(m, __shfl_xor_sync(0xffffffffu, m, o));
        float z = 0.f;
        for (int j = lane; j < deg; j += 32) {
            int s = g_csrc[base + j];
            float e = asrc[s * 5 + h] + ad;
            e = (e > 0.f) ? e : NEG_SLOPE * e;
            z += __expf(e - m);
        }
#pragma unroll
        for (int o = 16; o > 0; o >>= 1)
            z += __shfl_xor_sync(0xffffffffu, z, o);
        if (lane == 0) { s_m[h] = m; s_iz[h] = 1.f / (z + EPS_F); }
    }
    __syncthreads();

    float4 acc = make_float4(0.f, 0.f, 0.f, 0.f);
    int head = (tid * 4) / C;

    for (int j0 = 0; j0 < deg; j0 += CH) {
        int ch = min(CH, deg - j0);
        for (int idx = tid; idx < ch * 5; idx += 192) {
            int j = idx / 5, hh = idx - j * 5;
            int s = g_csrc[base + j0 + j];
            if (hh == 0) s_src[j] = s;
            float e = asrc[s * 5 + hh] + s_ad[hh];
            e = (e > 0.f) ? e : NEG_SLOPE * e;
            s_w[j * 5 + hh] = __expf(e - s_m[hh]) * s_iz[hh];
        }
        __syncthreads();
        if (tid < NC4) {
#pragma unroll 2
            for (int j = 0; j < ch; j++) {
                const float4* hp = (const float4*)(hfeat + (size_t)s_src[j] * HC);
                float w = s_w[j * 5 + head];
                float4 hv = hp[tid];
                acc.x += w * hv.x; acc.y += w * hv.y;
                acc.z += w * hv.z; acc.w += w * hv.w;
            }
        }
        __syncthreads();
    }

    if (tid < NC4) {
        float4 b = ((const float4*)bias)[tid];
        float4 o;
        o.x = fmaxf(acc.x + b.x, 0.f);
        o.y = fmaxf(acc.y + b.y, 0.f);
        o.z = fmaxf(acc.z + b.z, 0.f);
        o.w = fmaxf(acc.w + b.w, 0.f);
        ((float4*)(out + (size_t)v * HC))[tid] = o;
    }
}

// ---------------------------------------------------------------------------
// GAT aggregation, H=1, C=32: warp per node, lane = channel.
// ---------------------------------------------------------------------------
__global__ void __launch_bounds__(256)
gat_agg1(const float* __restrict__ hfeat,
         const float* __restrict__ asrc,
         const float* __restrict__ adst,
         const float* __restrict__ bias,
         float* __restrict__ out) {
    int wid = threadIdx.x >> 5, lane = threadIdx.x & 31;
    int v = blockIdx.x * 8 + wid;
    if (v >= N_NODES) return;
    int base = g_rowptr[v];
    int deg = g_rowptr[v + 1] - base;
    float ad = adst[v];

    float m = -INFINITY;
    for (int j = lane; j < deg; j += 32) {
        int s = g_csrc[base + j];
        float e = asrc[s] + ad;
        e = (e > 0.f) ? e : NEG_SLOPE * e;
        m = fmaxf(m, e);
    }
#pragma unroll
    for (int o = 16; o > 0; o >>= 1)
        m = fmaxf(m, __shfl_xor_sync(0xffffffffu, m, o));
    float z = 0.f;
    for (int j = lane; j < deg; j += 32) {
        int s = g_csrc[base + j];
        float e = asrc[s] + ad;
        e = (e > 0.f) ? e : NEG_SLOPE * e;
        z += __expf(e - m);
    }
#pragma unroll
    for (int o = 16; o > 0; o >>= 1)
        z += __shfl_xor_sync(0xffffffffu, z, o);
    float iz = 1.f / (z + EPS_F);

    float acc = 0.f;
#pragma unroll 2
    for (int j = 0; j < deg; j++) {
        int s = g_csrc[base + j];                 // warp-broadcast load
        float e = asrc[s] + ad;
        e = (e > 0.f) ? e : NEG_SLOPE * e;
        float w = __expf(e - m) * iz;
        acc += w * hfeat[(size_t)s * 32 + lane];
    }
    out[(size_t)v * 32 + lane] = fmaxf(acc + bias[lane], 0.f);
}

// ---------------------------------------------------------------------------
// global add pool + MLP head
// ---------------------------------------------------------------------------
__global__ void pool_kernel(const int* __restrict__ batch) {
    int i = blockIdx.x * blockDim.x + threadIdx.x;
    if (i >= N_NODES * 32) return;
    int n = i >> 5, c = i & 31;
    atomicAdd(&g_pool[batch[n] * 32 + c], g_o3[i]);
}

__global__ void mlp_kernel(const float* __restrict__ lin_w,
                           const float* __restrict__ lin_b,
                           const float* __restrict__ lin2_w,
                           const float* __restrict__ lin2_b,
                           float* __restrict__ out) {
    int g = blockIdx.x;
    __shared__ float sg[32];
    __shared__ float sred[256];
    int tid = threadIdx.x;
    if (tid < 32) sg[tid] = g_pool[g * 32 + tid];
    __syncthreads();
    float partial = 0.f;
    for (int u = tid; u < 1024; u += 256) {
        float d = lin_b[u];
        const float* wr = lin_w + u * 32;
#pragma unroll
        for (int c = 0; c < 32; c++) d += sg[c] * wr[c];
        d = fmaxf(d, 0.f);
        partial += d * lin2_w[u];
    }
    sred[tid] = partial;
    __syncthreads();
    for (int s = 128; s > 0; s >>= 1) {
        if (tid < s) sred[tid] += sred[tid + s];
        __syncthreads();
    }
    if (tid == 0) {
        float v = sred[0] + lin2_b[0];
        out[g] = 1.f / (1.f + __expf(-v));
    }
}

// ---------------------------------------------------------------------------
// launch
// ---------------------------------------------------------------------------
extern "C" void kernel_launch(void* const* d_in, const int* in_sizes, int n_in,
                              void* d_out, int out_size) {
    const float* x        = (const float*)d_in[0];
    const float* W1       = (const float*)d_in[1];
    const float* att_s1   = (const float*)d_in[2];
    const float* att_d1   = (const float*)d_in[3];
    const float* b1       = (const float*)d_in[4];
    const float* W2       = (const float*)d_in[5];
    const float* att_s2   = (const float*)d_in[6];
    const float* att_d2   = (const float*)d_in[7];
    const float* b2       = (const float*)d_in[8];
    const float* W3       = (const float*)d_in[9];
    const float* att_s3   = (const float*)d_in[10];
    const float* att_d3   = (const float*)d_in[11];
    const float* b3       = (const float*)d_in[12];
    const float* lin_w    = (const float*)d_in[13];
    const float* lin_b    = (const float*)d_in[14];
    const float* lin2_w   = (const float*)d_in[15];
    const float* lin2_b   = (const float*)d_in[16];
    const int*   ei       = (const int*)d_in[17];
    const int*   batch    = (const int*)d_in[18];
    float* out = (float*)d_out;

    float *h1, *o1, *h2, *o2, *h3, *o3, *asrc, *adst;
    cudaGetSymbolAddress((void**)&h1, g_h1);
    cudaGetSymbolAddress((void**)&o1, g_o1);
    cudaGetSymbolAddress((void**)&h2, g_h2);
    cudaGetSymbolAddress((void**)&o2, g_o2);
    cudaGetSymbolAddress((void**)&h3, g_h3);
    cudaGetSymbolAddress((void**)&o3, g_o3);
    cudaGetSymbolAddress((void**)&asrc, g_asrc);
    cudaGetSymbolAddress((void**)&adst, g_adst);

    // ---- CSR build (6 launches) ----
    init_kernel<<<N_BLK, 256>>>();
    count_kernel<<<(N_EDGES + 255) / 256, 256>>>(ei);
    scan1_kernel<<<N_BLK, 256>>>();
    scan2_kernel<<<1, 128>>>();
    scan3_kernel<<<N_BLK, 256>>>();
    scatter_kernel<<<(TOT_E + 255) / 256, 256>>>(ei);

    const int GY = (N_NODES + 127) / 128;

    // ---- Layer 1: 64 -> H=5, C=64 ----
    {
        dim3 grid((HC1 + 63) / 64, GY);
        gemm_tf32<<<grid, 256>>>(x, W1, h1, N_NODES, HC1, 64);
        int warps = N_NODES * 5;
        att_scores<<<(warps * 32 + 127) / 128, 128>>>(h1, att_s1, att_d1, asrc, adst, N_NODES, 5, 64);
        gat_agg5<64><<<N_NODES, 192>>>(h1, asrc, adst, b1, o1);
    }
    // ---- Layer 2: 320 -> H=5, C=96 ----
    {
        dim3 grid((HC2 + 63) / 64, GY);
        gemm_tf32<<<grid, 256>>>(o1, W2, h2, N_NODES, HC2, HC1);
        int warps = N_NODES * 5;
        att_scores<<<(warps * 32 + 127) / 128, 128>>>(h2, att_s2, att_d2, asrc, adst, N_NODES, 5, 96);
        gat_agg5<96><<<N_NODES, 192>>>(h2, asrc, adst, b2, o2);
    }
    // ---- Layer 3: 480 -> H=1, C=32 ----
    {
        dim3 grid((HC3 + 63) / 64, GY);
        gemm_tf32<<<grid, 256>>>(o2, W3, h3, N_NODES, HC3, HC2);
        att_scores<<<(N_NODES * 32 + 127) / 128, 128>>>(h3, att_s3, att_d3, asrc, adst, N_NODES, 1, 32);
        gat_agg1<<<(N_NODES + 7) / 8, 256>>>(h3, asrc, adst, b3, o3);
    }

    // ---- pool + MLP ----
    pool_kernel<<<(N_NODES * 32 + 255) / 256, 256>>>(batch);
    mlp_kernel<<<N_GRAPHS, 256>>>(lin_w, lin_b, lin2_w, lin2_b, out);
}

// round 4
// speedup vs baseline: 2.4922x; 1.1621x over previous
#include <cuda_runtime.h>
#include <cuda_bf16.h>
#include <math.h>
#include <stdint.h>

// ---------------------------------------------------------------------------
// Problem constants
// ---------------------------------------------------------------------------
#define N_NODES 20000
#define N_EDGES 320000
#define TOT_E   (N_EDGES + N_NODES)
#define N_GRAPHS 128
#define NEG_SLOPE 0.2f
#define EPS_F 1e-16f

#define HC1 320   // H=5, C=64
#define HC2 480   // H=5, C=96
#define HC3 32    // H=1, C=32

#define N_BLK ((N_NODES + 255) / 256)   // 79

// ---------------------------------------------------------------------------
// Device scratch
// ---------------------------------------------------------------------------
__device__ __align__(16) float g_h1[N_NODES * HC1];
__device__ __align__(16) float g_o1[N_NODES * HC1];
__device__ __align__(16) float g_h2[N_NODES * HC2];
__device__ __align__(16) float g_o2[N_NODES * HC2];
__device__ __align__(16) float g_h3[N_NODES * HC3];
__device__ float g_asrc[N_NODES * 5];
__device__ float g_adst[N_NODES * 5];
__device__ int   g_cnt[N_NODES];
__device__ int   g_rowptr[N_NODES + 1];
__device__ int   g_cursor[N_NODES];
__device__ int   g_csrc[TOT_E];
__device__ int   g_bsum[N_BLK];
__device__ float g_pool[N_GRAPHS * 32];

// ---------------------------------------------------------------------------
// CSR construction
// ---------------------------------------------------------------------------
__global__ void init_kernel() {
    int i = blockIdx.x * blockDim.x + threadIdx.x;
    if (i < N_NODES) g_cnt[i] = 1;                 // self loop pre-counted
    if (i < N_GRAPHS * 32) g_pool[i] = 0.f;
}

__global__ void count_kernel(const int* __restrict__ ei) {
    int i = blockIdx.x * blockDim.x + threadIdx.x;
    if (i < N_EDGES) atomicAdd(&g_cnt[ei[N_EDGES + i]], 1);
}

// block-local inclusive scan, publish block sums
__global__ void scan1_kernel() {
    int i = blockIdx.x * 256 + threadIdx.x;
    int lane = threadIdx.x & 31, w = threadIdx.x >> 5;
    int x = (i < N_NODES) ? g_cnt[i] : 0;
#pragma unroll
    for (int o = 1; o < 32; o <<= 1) {
        int t = __shfl_up_sync(0xffffffffu, x, o);
        if (lane >= o) x += t;
    }
    __shared__ int wsum[8];
    if (lane == 31) wsum[w] = x;
    __syncthreads();
    if (w == 0) {
        int s = (lane < 8) ? wsum[lane] : 0;
#pragma unroll
        for (int o = 1; o < 8; o <<= 1) {
            int t = __shfl_up_sync(0xffffffffu, s, o);
            if (lane >= o) s += t;
        }
        if (lane < 8) wsum[lane] = s;
    }
    __syncthreads();
    int incl = x + ((w > 0) ? wsum[w - 1] : 0);
    if (i < N_NODES) g_rowptr[i + 1] = incl;
    if (threadIdx.x == 255) g_bsum[blockIdx.x] = incl;
}

// each block sums its predecessor block sums itself (N_BLK=79, cheap),
// applies offset, writes cursor
__global__ void scan3_kernel() {
    __shared__ int s_off;
    int tid = threadIdx.x;
    if (tid == 0) {
        int off = 0;
        for (int j = 0; j < blockIdx.x; j++) off += g_bsum[j];
        s_off = off;
    }
    __syncthreads();
    int i = blockIdx.x * 256 + tid;
    if (i == 0) g_rowptr[0] = 0;
    if (i < N_NODES) {
        int incl = g_rowptr[i + 1] + s_off;
        g_rowptr[i + 1] = incl;
        g_cursor[i] = incl - g_cnt[i];
    }
}

// scatter edges + self loops in one pass
__global__ void scatter_kernel(const int* __restrict__ ei) {
    int i = blockIdx.x * blockDim.x + threadIdx.x;
    if (i >= TOT_E) return;
    int src, dst;
    if (i < N_EDGES) { src = ei[i]; dst = ei[N_EDGES + i]; }
    else             { src = dst = i - N_EDGES; }
    int pos = atomicAdd(&g_cursor[dst], 1);
    g_csrc[pos] = src;
}

// ---------------------------------------------------------------------------
// bf16 tensor-core GEMM: C[N,M] = A[N,K] * B[M,K]^T   (fp32 in/out, bf16 mma)
// BM=128, BN=64, BK=32 fp32 (16 packed bf16x2), 256 thr = 8 warps, 32x32/warp
// K % 32 == 0 (64, 320, 480 all OK).
// ---------------------------------------------------------------------------
__device__ __forceinline__ uint32_t pack_bf16x2(float lo, float hi) {
    __nv_bfloat162 h2 = __floats2bfloat162_rn(lo, hi);
    return *(uint32_t*)&h2;
}

__global__ void __launch_bounds__(256, 2)
gemm_bf16(const float* __restrict__ A, const float* __restrict__ B,
          float* __restrict__ C, int N, int M, int K) {
    const int BM = 128, BN = 64, BK2 = 16;   // 16 packed pairs = 32 fp32
    __shared__ uint32_t As[2][BM][BK2 + 2];
    __shared__ uint32_t Bs[2][BN][BK2 + 2];

    int tid  = threadIdx.x;
    int lane = tid & 31;
    int wid  = tid >> 5;
    int wr = (wid & 3) * 32;
    int wc = (wid >> 2) * 32;
    int gid = lane >> 2;
    int tig = lane & 3;

    int blockRow = blockIdx.y * BM;
    int blockCol = blockIdx.x * BN;

    // load coords: A 128x8 float4 (1024 -> 4/thr), B 64x8 float4 (512 -> 2/thr)
    float4 va[4], vb[2];
    const float4 zero4 = make_float4(0.f, 0.f, 0.f, 0.f);
    int arr[4], acc4[4], brr[2], bcc4[2];
#pragma unroll
    for (int l = 0; l < 4; l++) {
        int idx = tid + l * 256;
        arr[l] = idx >> 3;  acc4[l] = idx & 7;
    }
#pragma unroll
    for (int l = 0; l < 2; l++) {
        int idx = tid + l * 256;
        brr[l] = idx >> 3;  bcc4[l] = idx & 7;
    }

    auto loadTile = [&](int k0) {
#pragma unroll
        for (int l = 0; l < 4; l++)
            va[l] = (blockRow + arr[l] < N)
                  ? *(const float4*)(A + (size_t)(blockRow + arr[l]) * K + k0 + acc4[l] * 4) : zero4;
#pragma unroll
        for (int l = 0; l < 2; l++)
            vb[l] = (blockCol + brr[l] < M)
                  ? *(const float4*)(B + (size_t)(blockCol + brr[l]) * K + k0 + bcc4[l] * 4) : zero4;
    };
    auto storeTile = [&](int buf) {
#pragma unroll
        for (int l = 0; l < 4; l++) {
            As[buf][arr[l]][acc4[l] * 2]     = pack_bf16x2(va[l].x, va[l].y);
            As[buf][arr[l]][acc4[l] * 2 + 1] = pack_bf16x2(va[l].z, va[l].w);
        }
#pragma unroll
        for (int l = 0; l < 2; l++) {
            Bs[buf][brr[l]][bcc4[l] * 2]     = pack_bf16x2(vb[l].x, vb[l].y);
            Bs[buf][brr[l]][bcc4[l] * 2 + 1] = pack_bf16x2(vb[l].z, vb[l].w);
        }
    };

    float acc[2][4][4];
#pragma unroll
    for (int mt = 0; mt < 2; mt++)
#pragma unroll
        for (int nt = 0; nt < 4; nt++)
#pragma unroll
            for (int i = 0; i < 4; i++) acc[mt][nt][i] = 0.f;

    loadTile(0);
    storeTile(0);
    __syncthreads();

    int buf = 0;
    for (int k0 = 32; k0 <= K; k0 += 32) {
        bool has = (k0 < K);
        if (has) loadTile(k0);

#pragma unroll
        for (int ks = 0; ks < 2; ks++) {
            int kb = ks * 8;
            uint32_t a[2][4], b[4][2];
#pragma unroll
            for (int mt = 0; mt < 2; mt++) {
                int r0 = wr + mt * 16;
                a[mt][0] = As[buf][r0 + gid    ][kb + tig    ];
                a[mt][1] = As[buf][r0 + gid + 8][kb + tig    ];
                a[mt][2] = As[buf][r0 + gid    ][kb + tig + 4];
                a[mt][3] = As[buf][r0 + gid + 8][kb + tig + 4];
            }
#pragma unroll
            for (int nt = 0; nt < 4; nt++) {
                int n0 = wc + nt * 8 + gid;
                b[nt][0] = Bs[buf][n0][kb + tig    ];
                b[nt][1] = Bs[buf][n0][kb + tig + 4];
            }
#pragma unroll
            for (int mt = 0; mt < 2; mt++)
#pragma unroll
                for (int nt = 0; nt < 4; nt++) {
                    asm volatile(
                        "mma.sync.aligned.m16n8k16.row.col.f32.bf16.bf16.f32 "
                        "{%0,%1,%2,%3}, {%4,%5,%6,%7}, {%8,%9}, {%0,%1,%2,%3};"
                        : "+f"(acc[mt][nt][0]), "+f"(acc[mt][nt][1]),
                          "+f"(acc[mt][nt][2]), "+f"(acc[mt][nt][3])
                        : "r"(a[mt][0]), "r"(a[mt][1]), "r"(a[mt][2]), "r"(a[mt][3]),
                          "r"(b[nt][0]), "r"(b[nt][1]));
                }
        }

        if (has) storeTile(buf ^ 1);
        __syncthreads();
        buf ^= 1;
    }

#pragma unroll
    for (int mt = 0; mt < 2; mt++) {
#pragma unroll
        for (int nt = 0; nt < 4; nt++) {
            int r0 = blockRow + wr + mt * 16 + gid;
            int c0 = blockCol + wc + nt * 8 + tig * 2;
            if (c0 < M) {
                if (r0 < N) {
                    C[(size_t)r0 * M + c0]     = acc[mt][nt][0];
                    C[(size_t)r0 * M + c0 + 1] = acc[mt][nt][1];
                }
                if (r0 + 8 < N) {
                    C[(size_t)(r0 + 8) * M + c0]     = acc[mt][nt][2];
                    C[(size_t)(r0 + 8) * M + c0 + 1] = acc[mt][nt][3];
                }
            }
        }
    }
}

// ---------------------------------------------------------------------------
// attention scores, float4-vectorized: one warp per (n,h)
// ---------------------------------------------------------------------------
__global__ void att_scores(const float* __restrict__ h,
                           const float* __restrict__ att_src,
                           const float* __restrict__ att_dst,
                           float* __restrict__ asrc, float* __restrict__ adst,
                           int N, int H, int C) {
    int warp = (blockIdx.x * blockDim.x + threadIdx.x) >> 5;
    int lane = threadIdx.x & 31;
    if (warp >= N * H) return;
    int n = warp / H, hh = warp - n * H;
    float s = 0.f, d = 0.f;
    int nq = C >> 2;                    // 8/16/24 float4 per (n,h)
    if (lane < nq) {
        const float4* hp = (const float4*)(h + (size_t)n * H * C + hh * C);
        const float4* ap = (const float4*)(att_src + hh * C);
        const float4* dp = (const float4*)(att_dst + hh * C);
        float4 v = hp[lane], a = ap[lane], b = dp[lane];
        s = v.x * a.x + v.y * a.y + v.z * a.z + v.w * a.w;
        d = v.x * b.x + v.y * b.y + v.z * b.z + v.w * b.w;
    }
#pragma unroll
    for (int o = 16; o > 0; o >>= 1) {
        s += __shfl_down_sync(0xffffffffu, s, o);
        d += __shfl_down_sync(0xffffffffu, d, o);
    }
    if (lane == 0) { asrc[n * H + hh] = s; adst[n * H + hh] = d; }
}

// ---------------------------------------------------------------------------
// GAT aggregation, H=5, float4 channels. One block (192 thr) per node.
// ---------------------------------------------------------------------------
template<int C>
__global__ void __launch_bounds__(192)
gat_agg5(const float* __restrict__ hfeat,
         const float* __restrict__ asrc,
         const float* __restrict__ adst,
         const float* __restrict__ bias,
         float* __restrict__ out) {
    const int HC = 5 * C, NC4 = HC / 4;
    const int CH = 64;
    __shared__ float s_m[5], s_iz[5], s_ad[5];
    __shared__ int   s_src[CH];
    __shared__ float s_w[CH * 5];

    int v = blockIdx.x;
    int tid = threadIdx.x, lane = tid & 31, wid = tid >> 5;
    int base = g_rowptr[v];
    int deg = g_rowptr[v + 1] - base;

    if (tid < 5) s_ad[tid] = adst[v * 5 + tid];
    __syncthreads();

    if (wid < 5) {
        int h = wid;
        float ad = s_ad[h];
        float m = -INFINITY;
        for (int j = lane; j < deg; j += 32) {
            int s = g_csrc[base + j];
            float e = asrc[s * 5 + h] + ad;
            e = (e > 0.f) ? e : NEG_SLOPE * e;
            m = fmaxf(m, e);
        }
#pragma unroll
        for (int o = 16; o > 0; o >>= 1)
            m = fmaxf(m, __shfl_xor_sync(0xffffffffu, m, o));
        float z = 0.f;
        for (int j = lane; j < deg; j += 32) {
            int s = g_csrc[base + j];
            float e = asrc[s * 5 + h] + ad;
            e = (e > 0.f) ? e : NEG_SLOPE * e;
            z += __expf(e - m);
        }
#pragma unroll
        for (int o = 16; o > 0; o >>= 1)
            z += __shfl_xor_sync(0xffffffffu, z, o);
        if (lane == 0) { s_m[h] = m; s_iz[h] = 1.f / (z + EPS_F); }
    }
    __syncthreads();

    float4 acc = make_float4(0.f, 0.f, 0.f, 0.f);
    int head = (tid * 4) / C;

    for (int j0 = 0; j0 < deg; j0 += CH) {
        int ch = min(CH, deg - j0);
        for (int idx = tid; idx < ch * 5; idx += 192) {
            int j = idx / 5, hh = idx - j * 5;
            int s = g_csrc[base + j0 + j];
            if (hh == 0) s_src[j] = s;
            float e = asrc[s * 5 + hh] + s_ad[hh];
            e = (e > 0.f) ? e : NEG_SLOPE * e;
            s_w[j * 5 + hh] = __expf(e - s_m[hh]) * s_iz[hh];
        }
        __syncthreads();
        if (tid < NC4) {
#pragma unroll 2
            for (int j = 0; j < ch; j++) {
                const float4* hp = (const float4*)(hfeat + (size_t)s_src[j] * HC);
                float w = s_w[j * 5 + head];
                float4 hv = hp[tid];
                acc.x += w * hv.x; acc.y += w * hv.y;
                acc.z += w * hv.z; acc.w += w * hv.w;
            }
        }
        __syncthreads();
    }

    if (tid < NC4) {
        float4 b = ((const float4*)bias)[tid];
        float4 o;
        o.x = fmaxf(acc.x + b.x, 0.f);
        o.y = fmaxf(acc.y + b.y, 0.f);
        o.z = fmaxf(acc.z + b.z, 0.f);
        o.w = fmaxf(acc.w + b.w, 0.f);
        ((float4*)(out + (size_t)v * HC))[tid] = o;
    }
}

// ---------------------------------------------------------------------------
// GAT aggregation, H=1, C=32 + fused global_add_pool.
// warp per node, lane = channel.
// ---------------------------------------------------------------------------
__global__ void __launch_bounds__(256)
gat_agg1_pool(const float* __restrict__ hfeat,
              const float* __restrict__ asrc,
              const float* __restrict__ adst,
              const float* __restrict__ bias,
              const int* __restrict__ batch) {
    int wid = threadIdx.x >> 5, lane = threadIdx.x & 31;
    int v = blockIdx.x * 8 + wid;
    if (v >= N_NODES) return;
    int base = g_rowptr[v];
    int deg = g_rowptr[v + 1] - base;
    float ad = adst[v];

    float m = -INFINITY;
    for (int j = lane; j < deg; j += 32) {
        int s = g_csrc[base + j];
        float e = asrc[s] + ad;
        e = (e > 0.f) ? e : NEG_SLOPE * e;
        m = fmaxf(m, e);
    }
#pragma unroll
    for (int o = 16; o > 0; o >>= 1)
        m = fmaxf(m, __shfl_xor_sync(0xffffffffu, m, o));
    float z = 0.f;
    for (int j = lane; j < deg; j += 32) {
        int s = g_csrc[base + j];
        float e = asrc[s] + ad;
        e = (e > 0.f) ? e : NEG_SLOPE * e;
        z += __expf(e - m);
    }
#pragma unroll
    for (int o = 16; o > 0; o >>= 1)
        z += __shfl_xor_sync(0xffffffffu, z, o);
    float iz = 1.f / (z + EPS_F);

    float acc = 0.f;
#pragma unroll 2
    for (int j = 0; j < deg; j++) {
        int s = g_csrc[base + j];                 // warp-broadcast load
        float e = asrc[s] + ad;
        e = (e > 0.f) ? e : NEG_SLOPE * e;
        float w = __expf(e - m) * iz;
        acc += w * hfeat[(size_t)s * 32 + lane];
    }
    float o = fmaxf(acc + bias[lane], 0.f);
    atomicAdd(&g_pool[batch[v] * 32 + lane], o);
}

// ---------------------------------------------------------------------------
// MLP head
// ---------------------------------------------------------------------------
__global__ void mlp_kernel(const float* __restrict__ lin_w,
                           const float* __restrict__ lin_b,
                           const float* __restrict__ lin2_w,
                           const float* __restrict__ lin2_b,
                           float* __restrict__ out) {
    int g = blockIdx.x;
    __shared__ float sg[32];
    __shared__ float sred[256];
    int tid = threadIdx.x;
    if (tid < 32) sg[tid] = g_pool[g * 32 + tid];
    __syncthreads();
    float partial = 0.f;
    for (int u = tid; u < 1024; u += 256) {
        float d = lin_b[u];
        const float* wr = lin_w + u * 32;
#pragma unroll
        for (int c = 0; c < 32; c++) d += sg[c] * wr[c];
        d = fmaxf(d, 0.f);
        partial += d * lin2_w[u];
    }
    sred[tid] = partial;
    __syncthreads();
    for (int s = 128; s > 0; s >>= 1) {
        if (tid < s) sred[tid] += sred[tid + s];
        __syncthreads();
    }
    if (tid == 0) {
        float v = sred[0] + lin2_b[0];
        out[g] = 1.f / (1.f + __expf(-v));
    }
}

// ---------------------------------------------------------------------------
// launch
// ---------------------------------------------------------------------------
extern "C" void kernel_launch(void* const* d_in, const int* in_sizes, int n_in,
                              void* d_out, int out_size) {
    const float* x        = (const float*)d_in[0];
    const float* W1       = (const float*)d_in[1];
    const float* att_s1   = (const float*)d_in[2];
    const float* att_d1   = (const float*)d_in[3];
    const float* b1       = (const float*)d_in[4];
    const float* W2       = (const float*)d_in[5];
    const float* att_s2   = (const float*)d_in[6];
    const float* att_d2   = (const float*)d_in[7];
    const float* b2       = (const float*)d_in[8];
    const float* W3       = (const float*)d_in[9];
    const float* att_s3   = (const float*)d_in[10];
    const float* att_d3   = (const float*)d_in[11];
    const float* b3       = (const float*)d_in[12];
    const float* lin_w    = (const float*)d_in[13];
    const float* lin_b    = (const float*)d_in[14];
    const float* lin2_w   = (const float*)d_in[15];
    const float* lin2_b   = (const float*)d_in[16];
    const int*   ei       = (const int*)d_in[17];
    const int*   batch    = (const int*)d_in[18];
    float* out = (float*)d_out;

    float *h1, *o1, *h2, *o2, *h3, *asrc, *adst;
    cudaGetSymbolAddress((void**)&h1, g_h1);
    cudaGetSymbolAddress((void**)&o1, g_o1);
    cudaGetSymbolAddress((void**)&h2, g_h2);
    cudaGetSymbolAddress((void**)&o2, g_o2);
    cudaGetSymbolAddress((void**)&h3, g_h3);
    cudaGetSymbolAddress((void**)&asrc, g_asrc);
    cudaGetSymbolAddress((void**)&adst, g_adst);

    // ---- CSR build (5 launches) ----
    init_kernel<<<N_BLK, 256>>>();
    count_kernel<<<(N_EDGES + 255) / 256, 256>>>(ei);
    scan1_kernel<<<N_BLK, 256>>>();
    scan3_kernel<<<N_BLK, 256>>>();
    scatter_kernel<<<(TOT_E + 255) / 256, 256>>>(ei);

    const int GY = (N_NODES + 127) / 128;

    // ---- Layer 1: 64 -> H=5, C=64 ----
    {
        dim3 grid((HC1 + 63) / 64, GY);
        gemm_bf16<<<grid, 256>>>(x, W1, h1, N_NODES, HC1, 64);
        int warps = N_NODES * 5;
        att_scores<<<(warps * 32 + 255) / 256, 256>>>(h1, att_s1, att_d1, asrc, adst, N_NODES, 5, 64);
        gat_agg5<64><<<N_NODES, 192>>>(h1, asrc, adst, b1, o1);
    }
    // ---- Layer 2: 320 -> H=5, C=96 ----
    {
        dim3 grid((HC2 + 63) / 64, GY);
        gemm_bf16<<<grid, 256>>>(o1, W2, h2, N_NODES, HC2, HC1);
        int warps = N_NODES * 5;
        att_scores<<<(warps * 32 + 255) / 256, 256>>>(h2, att_s2, att_d2, asrc, adst, N_NODES, 5, 96);
        gat_agg5<96><<<N_NODES, 192>>>(h2, asrc, adst, b2, o2);
    }
    // ---- Layer 3: 480 -> H=1, C=32 (agg fused with pool) ----
    {
        dim3 grid((HC3 + 63) / 64, GY);
        gemm_bf16<<<grid, 256>>>(o2, W3, h3, N_NODES, HC3, HC2);
        att_scores<<<(N_NODES * 32 + 255) / 256, 256>>>(h3, att_s3, att_d3, asrc, adst, N_NODES, 1, 32);
        gat_agg1_pool<<<(N_NODES + 7) / 8, 256>>>(h3, asrc, adst, b3, batch);
    }

    // ---- MLP head ----
    mlp_kernel<<<N_GRAPHS, 256>>>(lin_w, lin_b, lin2_w, lin2_b, out);
}

// round 5
// speedup vs baseline: 2.5922x; 1.0401x over previous
#include <cuda_runtime.h>
#include <cuda_bf16.h>
#include <math.h>
#include <stdint.h>

// ---------------------------------------------------------------------------
// Problem constants
// ---------------------------------------------------------------------------
#define N_NODES 20000
#define N_EDGES 320000
#define TOT_E   (N_EDGES + N_NODES)
#define N_GRAPHS 128
#define NEG_SLOPE 0.2f
#define EPS_F 1e-16f

#define HC1 320   // H=5, C=64
#define HC2 480   // H=5, C=96
#define HC3 32    // H=1, C=32

#define N_BLK ((N_NODES + 255) / 256)   // 79

// ---------------------------------------------------------------------------
// Device scratch. h buffers are bf16 (halves gather traffic); o buffers fp32.
// ---------------------------------------------------------------------------
__device__ __align__(16) __nv_bfloat16 g_h1[N_NODES * HC1];
__device__ __align__(16) float         g_o1[N_NODES * HC1];
__device__ __align__(16) __nv_bfloat16 g_h2[N_NODES * HC2];
__device__ __align__(16) float         g_o2[N_NODES * HC2];
__device__ __align__(16) __nv_bfloat16 g_h3[N_NODES * HC3];
__device__ float g_asrc[N_NODES * 5];
__device__ float g_adst[N_NODES * 5];
__device__ int   g_cnt[N_NODES];
__device__ int   g_rowptr[N_NODES + 1];
__device__ int   g_cursor[N_NODES];
__device__ int   g_csrc[TOT_E];
__device__ int   g_bsum[N_BLK];
__device__ float g_pool[N_GRAPHS * 32];

// ---------------------------------------------------------------------------
// CSR construction (g_cnt memset to 0 beforehand; self-loop folded as +1)
// ---------------------------------------------------------------------------
__global__ void count_kernel(const int* __restrict__ ei) {
    int i = blockIdx.x * blockDim.x + threadIdx.x;
    if (i < N_EDGES) atomicAdd(&g_cnt[ei[N_EDGES + i]], 1);
}

// block-local inclusive scan of (cnt+1), publish block sums
__global__ void scan1_kernel() {
    int i = blockIdx.x * 256 + threadIdx.x;
    int lane = threadIdx.x & 31, w = threadIdx.x >> 5;
    int x = (i < N_NODES) ? (g_cnt[i] + 1) : 0;
#pragma unroll
    for (int o = 1; o < 32; o <<= 1) {
        int t = __shfl_up_sync(0xffffffffu, x, o);
        if (lane >= o) x += t;
    }
    __shared__ int wsum[8];
    if (lane == 31) wsum[w] = x;
    __syncthreads();
    if (w == 0) {
        int s = (lane < 8) ? wsum[lane] : 0;
#pragma unroll
        for (int o = 1; o < 8; o <<= 1) {
            int t = __shfl_up_sync(0xffffffffu, s, o);
            if (lane >= o) s += t;
        }
        if (lane < 8) wsum[lane] = s;
    }
    __syncthreads();
    int incl = x + ((w > 0) ? wsum[w - 1] : 0);
    if (i < N_NODES) g_rowptr[i + 1] = incl;
    if (threadIdx.x == 255) g_bsum[blockIdx.x] = incl;
}

// warp-parallel predecessor-sum, apply offset, write cursor
__global__ void scan3_kernel() {
    __shared__ int s_off;
    int tid = threadIdx.x, lane = tid & 31;
    if (tid < 32) {
        int off = 0;
        for (int j = lane; j < blockIdx.x; j += 32) off += g_bsum[j];
#pragma unroll
        for (int o = 16; o > 0; o >>= 1)
            off += __shfl_xor_sync(0xffffffffu, off, o);
        if (lane == 0) s_off = off;
    }
    __syncthreads();
    int i = blockIdx.x * 256 + tid;
    if (i == 0) g_rowptr[0] = 0;
    if (i < N_NODES) {
        int incl = g_rowptr[i + 1] + s_off;
        g_rowptr[i + 1] = incl;
        g_cursor[i] = incl - (g_cnt[i] + 1);
    }
}

// scatter edges + self loops in one pass
__global__ void scatter_kernel(const int* __restrict__ ei) {
    int i = blockIdx.x * blockDim.x + threadIdx.x;
    if (i >= TOT_E) return;
    int src, dst;
    if (i < N_EDGES) { src = ei[i]; dst = ei[N_EDGES + i]; }
    else             { src = dst = i - N_EDGES; }
    int pos = atomicAdd(&g_cursor[dst], 1);
    g_csrc[pos] = src;
}

// ---------------------------------------------------------------------------
// bf16 tensor-core GEMM: C[N,M](bf16) = A[N,K](fp32) * B[M,K]^T(fp32)
// BM=128, BN=64, BK=32 fp32 (16 packed bf16x2), 256 thr = 8 warps, 32x32/warp
// ---------------------------------------------------------------------------
__device__ __forceinline__ uint32_t pack_bf16x2(float lo, float hi) {
    __nv_bfloat162 h2 = __floats2bfloat162_rn(lo, hi);
    return *(uint32_t*)&h2;
}

__global__ void __launch_bounds__(256, 2)
gemm_bf16(const float* __restrict__ A, const float* __restrict__ B,
          __nv_bfloat16* __restrict__ C, int N, int M, int K) {
    const int BM = 128, BK2 = 16;
    __shared__ uint32_t As[2][BM][BK2 + 2];
    __shared__ uint32_t Bs[2][64][BK2 + 2];

    int tid  = threadIdx.x;
    int lane = tid & 31;
    int wid  = tid >> 5;
    int wr = (wid & 3) * 32;
    int wc = (wid >> 2) * 32;
    int gid = lane >> 2;
    int tig = lane & 3;

    int blockRow = blockIdx.y * BM;
    int blockCol = blockIdx.x * 64;

    float4 va[4], vb[2];
    const float4 zero4 = make_float4(0.f, 0.f, 0.f, 0.f);
    int arr[4], acc4[4], brr[2], bcc4[2];
#pragma unroll
    for (int l = 0; l < 4; l++) {
        int idx = tid + l * 256;
        arr[l] = idx >> 3;  acc4[l] = idx & 7;
    }
#pragma unroll
    for (int l = 0; l < 2; l++) {
        int idx = tid + l * 256;
        brr[l] = idx >> 3;  bcc4[l] = idx & 7;
    }

    auto loadTile = [&](int k0) {
#pragma unroll
        for (int l = 0; l < 4; l++)
            va[l] = (blockRow + arr[l] < N)
                  ? *(const float4*)(A + (size_t)(blockRow + arr[l]) * K + k0 + acc4[l] * 4) : zero4;
#pragma unroll
        for (int l = 0; l < 2; l++)
            vb[l] = (blockCol + brr[l] < M)
                  ? *(const float4*)(B + (size_t)(blockCol + brr[l]) * K + k0 + bcc4[l] * 4) : zero4;
    };
    auto storeTile = [&](int buf) {
#pragma unroll
        for (int l = 0; l < 4; l++) {
            As[buf][arr[l]][acc4[l] * 2]     = pack_bf16x2(va[l].x, va[l].y);
            As[buf][arr[l]][acc4[l] * 2 + 1] = pack_bf16x2(va[l].z, va[l].w);
        }
#pragma unroll
        for (int l = 0; l < 2; l++) {
            Bs[buf][brr[l]][bcc4[l] * 2]     = pack_bf16x2(vb[l].x, vb[l].y);
            Bs[buf][brr[l]][bcc4[l] * 2 + 1] = pack_bf16x2(vb[l].z, vb[l].w);
        }
    };

    float acc[2][4][4];
#pragma unroll
    for (int mt = 0; mt < 2; mt++)
#pragma unroll
        for (int nt = 0; nt < 4; nt++)
#pragma unroll
            for (int i = 0; i < 4; i++) acc[mt][nt][i] = 0.f;

    loadTile(0);
    storeTile(0);
    __syncthreads();

    int buf = 0;
    for (int k0 = 32; k0 <= K; k0 += 32) {
        bool has = (k0 < K);
        if (has) loadTile(k0);

#pragma unroll
        for (int ks = 0; ks < 2; ks++) {
            int kb = ks * 8;
            uint32_t a[2][4], b[4][2];
#pragma unroll
            for (int mt = 0; mt < 2; mt++) {
                int r0 = wr + mt * 16;
                a[mt][0] = As[buf][r0 + gid    ][kb + tig    ];
                a[mt][1] = As[buf][r0 + gid + 8][kb + tig    ];
                a[mt][2] = As[buf][r0 + gid    ][kb + tig + 4];
                a[mt][3] = As[buf][r0 + gid + 8][kb + tig + 4];
            }
#pragma unroll
            for (int nt = 0; nt < 4; nt++) {
                int n0 = wc + nt * 8 + gid;
                b[nt][0] = Bs[buf][n0][kb + tig    ];
                b[nt][1] = Bs[buf][n0][kb + tig + 4];
            }
#pragma unroll
            for (int mt = 0; mt < 2; mt++)
#pragma unroll
                for (int nt = 0; nt < 4; nt++) {
                    asm volatile(
                        "mma.sync.aligned.m16n8k16.row.col.f32.bf16.bf16.f32 "
                        "{%0,%1,%2,%3}, {%4,%5,%6,%7}, {%8,%9}, {%0,%1,%2,%3};"
                        : "+f"(acc[mt][nt][0]), "+f"(acc[mt][nt][1]),
                          "+f"(acc[mt][nt][2]), "+f"(acc[mt][nt][3])
                        : "r"(a[mt][0]), "r"(a[mt][1]), "r"(a[mt][2]), "r"(a[mt][3]),
                          "r"(b[nt][0]), "r"(b[nt][1]));
                }
        }

        if (has) storeTile(buf ^ 1);
        __syncthreads();
        buf ^= 1;
    }

    // epilogue: write bf16 pairs (4B each)
#pragma unroll
    for (int mt = 0; mt < 2; mt++) {
#pragma unroll
        for (int nt = 0; nt < 4; nt++) {
            int r0 = blockRow + wr + mt * 16 + gid;
            int c0 = blockCol + wc + nt * 8 + tig * 2;
            if (c0 < M) {
                if (r0 < N)
                    *(uint32_t*)(C + (size_t)r0 * M + c0) =
                        pack_bf16x2(acc[mt][nt][0], acc[mt][nt][1]);
                if (r0 + 8 < N)
                    *(uint32_t*)(C + (size_t)(r0 + 8) * M + c0) =
                        pack_bf16x2(acc[mt][nt][2], acc[mt][nt][3]);
            }
        }
    }
}

// ---------------------------------------------------------------------------
// attention scores from bf16 h: one warp per (n,h); lane = 4 channels
// ---------------------------------------------------------------------------
__global__ void att_scores(const __nv_bfloat16* __restrict__ h,
                           const float* __restrict__ att_src,
                           const float* __restrict__ att_dst,
                           float* __restrict__ asrc, float* __restrict__ adst,
                           int N, int H, int C) {
    int warp = (blockIdx.x * blockDim.x + threadIdx.x) >> 5;
    int lane = threadIdx.x & 31;
    if (warp >= N * H) return;
    int n = warp / H, hh = warp - n * H;
    float s = 0.f, d = 0.f;
    int nq = C >> 2;
    if (lane < nq) {
        const uint2* hp = (const uint2*)(h + (size_t)n * H * C + hh * C);
        uint2 hv = hp[lane];
        float2 f0 = __bfloat1622float2(*(__nv_bfloat162*)&hv.x);
        float2 f1 = __bfloat1622float2(*(__nv_bfloat162*)&hv.y);
        float4 a = ((const float4*)(att_src + hh * C))[lane];
        float4 b = ((const float4*)(att_dst + hh * C))[lane];
        s = f0.x * a.x + f0.y * a.y + f1.x * a.z + f1.y * a.w;
        d = f0.x * b.x + f0.y * b.y + f1.x * b.z + f1.y * b.w;
    }
#pragma unroll
    for (int o = 16; o > 0; o >>= 1) {
        s += __shfl_down_sync(0xffffffffu, s, o);
        d += __shfl_down_sync(0xffffffffu, d, o);
    }
    if (lane == 0) { asrc[n * H + hh] = s; adst[n * H + hh] = d; }
}

// ---------------------------------------------------------------------------
// GAT aggregation, H=5, bf16 gathers (uint2 = 4 ch). One block (192 thr)/node.
// ---------------------------------------------------------------------------
template<int C>
__global__ void __launch_bounds__(192)
gat_agg5(const __nv_bfloat16* __restrict__ hfeat,
         const float* __restrict__ asrc,
         const float* __restrict__ adst,
         const float* __restrict__ bias,
         float* __restrict__ out) {
    const int HC = 5 * C, NC4 = HC / 4;
    const int CH = 64;
    __shared__ float s_m[5], s_iz[5], s_ad[5];
    __shared__ int   s_src[CH];
    __shared__ float s_w[CH * 5];

    int v = blockIdx.x;
    int tid = threadIdx.x, lane = tid & 31, wid = tid >> 5;
    int base = g_rowptr[v];
    int deg = g_rowptr[v + 1] - base;

    if (tid < 5) s_ad[tid] = adst[v * 5 + tid];
    __syncthreads();

    if (wid < 5) {
        int h = wid;
        float ad = s_ad[h];
        float m = -INFINITY;
        for (int j = lane; j < deg; j += 32) {
            int s = g_csrc[base + j];
            float e = asrc[s * 5 + h] + ad;
            e = (e > 0.f) ? e : NEG_SLOPE * e;
            m = fmaxf(m, e);
        }
#pragma unroll
        for (int o = 16; o > 0; o >>= 1)
            m = fmaxf(m, __shfl_xor_sync(0xffffffffu, m, o));
        float z = 0.f;
        for (int j = lane; j < deg; j += 32) {
            int s = g_csrc[base + j];
            float e = asrc[s * 5 + h] + ad;
            e = (e > 0.f) ? e : NEG_SLOPE * e;
            z += __expf(e - m);
        }
#pragma unroll
        for (int o = 16; o > 0; o >>= 1)
            z += __shfl_xor_sync(0xffffffffu, z, o);
        if (lane == 0) { s_m[h] = m; s_iz[h] = 1.f / (z + EPS_F); }
    }
    __syncthreads();

    float4 acc = make_float4(0.f, 0.f, 0.f, 0.f);
    int head = (tid * 4) / C;

    for (int j0 = 0; j0 < deg; j0 += CH) {
        int ch = min(CH, deg - j0);
        for (int idx = tid; idx < ch * 5; idx += 192) {
            int j = idx / 5, hh = idx - j * 5;
            int s = g_csrc[base + j0 + j];
            if (hh == 0) s_src[j] = s;
            float e = asrc[s * 5 + hh] + s_ad[hh];
            e = (e > 0.f) ? e : NEG_SLOPE * e;
            s_w[j * 5 + hh] = __expf(e - s_m[hh]) * s_iz[hh];
        }
        __syncthreads();
        if (tid < NC4) {
#pragma unroll 2
            for (int j = 0; j < ch; j++) {
                const uint2* hp = (const uint2*)(hfeat + (size_t)s_src[j] * HC);
                float w = s_w[j * 5 + head];
                uint2 hv = hp[tid];
                float2 lo = __bfloat1622float2(*(__nv_bfloat162*)&hv.x);
                float2 hi = __bfloat1622float2(*(__nv_bfloat162*)&hv.y);
                acc.x += w * lo.x; acc.y += w * lo.y;
                acc.z += w * hi.x; acc.w += w * hi.y;
            }
        }
        __syncthreads();
    }

    if (tid < NC4) {
        float4 b = ((const float4*)bias)[tid];
        float4 o;
        o.x = fmaxf(acc.x + b.x, 0.f);
        o.y = fmaxf(acc.y + b.y, 0.f);
        o.z = fmaxf(acc.z + b.z, 0.f);
        o.w = fmaxf(acc.w + b.w, 0.f);
        ((float4*)(out + (size_t)v * HC))[tid] = o;
    }
}

// ---------------------------------------------------------------------------
// GAT aggregation, H=1, C=32 + fused global_add_pool. warp per node.
// ---------------------------------------------------------------------------
__global__ void __launch_bounds__(256)
gat_agg1_pool(const __nv_bfloat16* __restrict__ hfeat,
              const float* __restrict__ asrc,
              const float* __restrict__ adst,
              const float* __restrict__ bias,
              const int* __restrict__ batch) {
    int wid = threadIdx.x >> 5, lane = threadIdx.x & 31;
    int v = blockIdx.x * 8 + wid;
    if (v >= N_NODES) return;
    int base = g_rowptr[v];
    int deg = g_rowptr[v + 1] - base;
    float ad = adst[v];

    float m = -INFINITY;
    for (int j = lane; j < deg; j += 32) {
        int s = g_csrc[base + j];
        float e = asrc[s] + ad;
        e = (e > 0.f) ? e : NEG_SLOPE * e;
        m = fmaxf(m, e);
    }
#pragma unroll
    for (int o = 16; o > 0; o >>= 1)
        m = fmaxf(m, __shfl_xor_sync(0xffffffffu, m, o));
    float z = 0.f;
    for (int j = lane; j < deg; j += 32) {
        int s = g_csrc[base + j];
        float e = asrc[s] + ad;
        e = (e > 0.f) ? e : NEG_SLOPE * e;
        z += __expf(e - m);
    }
#pragma unroll
    for (int o = 16; o > 0; o >>= 1)
        z += __shfl_xor_sync(0xffffffffu, z, o);
    float iz = 1.f / (z + EPS_F);

    float acc = 0.f;
#pragma unroll 2
    for (int j = 0; j < deg; j++) {
        int s = g_csrc[base + j];
        float e = asrc[s] + ad;
        e = (e > 0.f) ? e : NEG_SLOPE * e;
        float w = __expf(e - m) * iz;
        acc += w * __bfloat162float(hfeat[(size_t)s * 32 + lane]);
    }
    float o = fmaxf(acc + bias[lane], 0.f);
    atomicAdd(&g_pool[batch[v] * 32 + lane], o);
}

// ---------------------------------------------------------------------------
// MLP head
// ---------------------------------------------------------------------------
__global__ void mlp_kernel(const float* __restrict__ lin_w,
                           const float* __restrict__ lin_b,
                           const float* __restrict__ lin2_w,
                           const float* __restrict__ lin2_b,
                           float* __restrict__ out) {
    int g = blockIdx.x;
    __shared__ float sg[32];
    __shared__ float sred[256];
    int tid = threadIdx.x;
    if (tid < 32) sg[tid] = g_pool[g * 32 + tid];
    __syncthreads();
    float partial = 0.f;
    for (int u = tid; u < 1024; u += 256) {
        float d = lin_b[u];
        const float* wr = lin_w + u * 32;
#pragma unroll
        for (int c = 0; c < 32; c++) d += sg[c] * wr[c];
        d = fmaxf(d, 0.f);
        partial += d * lin2_w[u];
    }
    sred[tid] = partial;
    __syncthreads();
    for (int s = 128; s > 0; s >>= 1) {
        if (tid < s) sred[tid] += sred[tid + s];
        __syncthreads();
    }
    if (tid == 0) {
        float v = sred[0] + lin2_b[0];
        out[g] = 1.f / (1.f + __expf(-v));
    }
}

// ---------------------------------------------------------------------------
// launch
// ---------------------------------------------------------------------------
extern "C" void kernel_launch(void* const* d_in, const int* in_sizes, int n_in,
                              void* d_out, int out_size) {
    const float* x        = (const float*)d_in[0];
    const float* W1       = (const float*)d_in[1];
    const float* att_s1   = (const float*)d_in[2];
    const float* att_d1   = (const float*)d_in[3];
    const float* b1       = (const float*)d_in[4];
    const float* W2       = (const float*)d_in[5];
    const float* att_s2   = (const float*)d_in[6];
    const float* att_d2   = (const float*)d_in[7];
    const float* b2       = (const float*)d_in[8];
    const float* W3       = (const float*)d_in[9];
    const float* att_s3   = (const float*)d_in[10];
    const float* att_d3   = (const float*)d_in[11];
    const float* b3       = (const float*)d_in[12];
    const float* lin_w    = (const float*)d_in[13];
    const float* lin_b    = (const float*)d_in[14];
    const float* lin2_w   = (const float*)d_in[15];
    const float* lin2_b   = (const float*)d_in[16];
    const int*   ei       = (const int*)d_in[17];
    const int*   batch    = (const int*)d_in[18];
    float* out = (float*)d_out;

    __nv_bfloat16 *h1, *h2, *h3;
    float *o1, *o2, *asrc, *adst, *pool;
    int *cnt;
    cudaGetSymbolAddress((void**)&h1, g_h1);
    cudaGetSymbolAddress((void**)&o1, g_o1);
    cudaGetSymbolAddress((void**)&h2, g_h2);
    cudaGetSymbolAddress((void**)&o2, g_o2);
    cudaGetSymbolAddress((void**)&h3, g_h3);
    cudaGetSymbolAddress((void**)&asrc, g_asrc);
    cudaGetSymbolAddress((void**)&adst, g_adst);
    cudaGetSymbolAddress((void**)&pool, g_pool);
    cudaGetSymbolAddress((void**)&cnt, g_cnt);

    // static side stream + events (created on first, non-capture call)
    static cudaStream_t s_cs = nullptr;
    static cudaEvent_t ev_fork = nullptr, ev_join = nullptr;
    if (!s_cs) {
        cudaStreamCreateWithFlags(&s_cs, cudaStreamNonBlocking);
        cudaEventCreateWithFlags(&ev_fork, cudaEventDisableTiming);
        cudaEventCreateWithFlags(&ev_join, cudaEventDisableTiming);
    }

    // ---- fork: CSR build on side stream ----
    cudaEventRecord(ev_fork, 0);
    cudaStreamWaitEvent(s_cs, ev_fork, 0);
    cudaMemsetAsync(cnt, 0, N_NODES * sizeof(int), s_cs);
    count_kernel<<<(N_EDGES + 255) / 256, 256, 0, s_cs>>>(ei);
    scan1_kernel<<<N_BLK, 256, 0, s_cs>>>();
    scan3_kernel<<<N_BLK, 256, 0, s_cs>>>();
    scatter_kernel<<<(TOT_E + 255) / 256, 256, 0, s_cs>>>(ei);
    cudaEventRecord(ev_join, s_cs);

    // ---- main stream: pool zero + GEMM1 + att1 (independent of CSR) ----
    cudaMemsetAsync(pool, 0, N_GRAPHS * 32 * sizeof(float), 0);

    const int GY = (N_NODES + 127) / 128;

    {
        dim3 grid((HC1 + 63) / 64, GY);
        gemm_bf16<<<grid, 256>>>(x, W1, h1, N_NODES, HC1, 64);
        int warps = N_NODES * 5;
        att_scores<<<(warps * 32 + 255) / 256, 256>>>(h1, att_s1, att_d1, asrc, adst, N_NODES, 5, 64);
    }

    // ---- join: aggregation needs CSR ----
    cudaStreamWaitEvent(0, ev_join, 0);
    gat_agg5<64><<<N_NODES, 192>>>(h1, asrc, adst, b1, o1);

    // ---- Layer 2: 320 -> H=5, C=96 ----
    {
        dim3 grid((HC2 + 63) / 64, GY);
        gemm_bf16<<<grid, 256>>>(o1, W2, h2, N_NODES, HC2, HC1);
        int warps = N_NODES * 5;
        att_scores<<<(warps * 32 + 255) / 256, 256>>>(h2, att_s2, att_d2, asrc, adst, N_NODES, 5, 96);
        gat_agg5<96><<<N_NODES, 192>>>(h2, asrc, adst, b2, o2);
    }
    // ---- Layer 3: 480 -> H=1, C=32 (agg fused with pool) ----
    {
        dim3 grid((HC3 + 63) / 64, GY);
        gemm_bf16<<<grid, 256>>>(o2, W3, h3, N_NODES, HC3, HC2);
        att_scores<<<(N_NODES * 32 + 255) / 256, 256>>>(h3, att_s3, att_d3, asrc, adst, N_NODES, 1, 32);
        gat_agg1_pool<<<(N_NODES + 7) / 8, 256>>>(h3, asrc, adst, b3, batch);
    }

    // ---- MLP head ----
    mlp_kernel<<<N_GRAPHS, 256>>>(lin_w, lin_b, lin2_w, lin2_b, out);
}

// round 6
// speedup vs baseline: 2.7597x; 1.0646x over previous
#include <cuda_runtime.h>
#include <cuda_bf16.h>
#include <math.h>
#include <stdint.h>

// ---------------------------------------------------------------------------
// Problem constants
// ---------------------------------------------------------------------------
#define N_NODES 20000
#define N_EDGES 320000
#define TOT_E   (N_EDGES + N_NODES)
#define N_GRAPHS 128
#define NEG_SLOPE 0.2f
#define EPS_F 1e-16f

#define HC1 320   // H=5, C=64
#define HC2 480   // H=5, C=96
#define HC3 32    // H=1, C=32

#define N_BLK ((N_NODES + 255) / 256)   // 79

// ---------------------------------------------------------------------------
// Device scratch. All GEMM A-operands and h buffers are bf16.
// ---------------------------------------------------------------------------
__device__ __align__(16) __nv_bfloat16 g_xq[N_NODES * 64];
__device__ __align__(16) __nv_bfloat16 g_h1[N_NODES * HC1];
__device__ __align__(16) __nv_bfloat16 g_o1[N_NODES * HC1];
__device__ __align__(16) __nv_bfloat16 g_h2[N_NODES * HC2];
__device__ __align__(16) __nv_bfloat16 g_o2[N_NODES * HC2];
__device__ __align__(16) __nv_bfloat16 g_h3[N_NODES * HC3];
__device__ float g_att[6 * N_NODES * 5];     // [layer][src/dst][N*5], zeroed once
__device__ int   g_cnt[N_NODES];
__device__ int   g_rowptr[N_NODES + 1];
__device__ int   g_cursor[N_NODES];
__device__ int   g_csrc[TOT_E];
__device__ int   g_bsum[N_BLK];
__device__ float g_pool[N_GRAPHS * 32];

__device__ __forceinline__ uint32_t pack_bf16x2(float lo, float hi) {
    __nv_bfloat162 h2 = __floats2bfloat162_rn(lo, hi);
    return *(uint32_t*)&h2;
}

// ---------------------------------------------------------------------------
// x -> bf16
// ---------------------------------------------------------------------------
__global__ void convert_x(const float* __restrict__ x) {
    int i = blockIdx.x * 256 + threadIdx.x;
    if (i < N_NODES * 64 / 4) {
        float4 v = ((const float4*)x)[i];
        uint2 p;
        p.x = pack_bf16x2(v.x, v.y);
        p.y = pack_bf16x2(v.z, v.w);
        ((uint2*)g_xq)[i] = p;
    }
}

// ---------------------------------------------------------------------------
// CSR construction (g_cnt memset to 0 beforehand; self-loop folded as +1)
// ---------------------------------------------------------------------------
__global__ void count_kernel(const int* __restrict__ ei) {
    int i = blockIdx.x * blockDim.x + threadIdx.x;
    if (i < N_EDGES) atomicAdd(&g_cnt[ei[N_EDGES + i]], 1);
}

__global__ void scan1_kernel() {
    int i = blockIdx.x * 256 + threadIdx.x;
    int lane = threadIdx.x & 31, w = threadIdx.x >> 5;
    int x = (i < N_NODES) ? (g_cnt[i] + 1) : 0;
#pragma unroll
    for (int o = 1; o < 32; o <<= 1) {
        int t = __shfl_up_sync(0xffffffffu, x, o);
        if (lane >= o) x += t;
    }
    __shared__ int wsum[8];
    if (lane == 31) wsum[w] = x;
    __syncthreads();
    if (w == 0) {
        int s = (lane < 8) ? wsum[lane] : 0;
#pragma unroll
        for (int o = 1; o < 8; o <<= 1) {
            int t = __shfl_up_sync(0xffffffffu, s, o);
            if (lane >= o) s += t;
        }
        if (lane < 8) wsum[lane] = s;
    }
    __syncthreads();
    int incl = x + ((w > 0) ? wsum[w - 1] : 0);
    if (i < N_NODES) g_rowptr[i + 1] = incl;
    if (threadIdx.x == 255) g_bsum[blockIdx.x] = incl;
}

__global__ void scan3_kernel() {
    __shared__ int s_off;
    int tid = threadIdx.x, lane = tid & 31;
    if (tid < 32) {
        int off = 0;
        for (int j = lane; j < blockIdx.x; j += 32) off += g_bsum[j];
#pragma unroll
        for (int o = 16; o > 0; o >>= 1)
            off += __shfl_xor_sync(0xffffffffu, off, o);
        if (lane == 0) s_off = off;
    }
    __syncthreads();
    int i = blockIdx.x * 256 + tid;
    if (i == 0) g_rowptr[0] = 0;
    if (i < N_NODES) {
        int incl = g_rowptr[i + 1] + s_off;
        g_rowptr[i + 1] = incl;
        g_cursor[i] = incl - (g_cnt[i] + 1);
    }
}

__global__ void scatter_kernel(const int* __restrict__ ei) {
    int i = blockIdx.x * blockDim.x + threadIdx.x;
    if (i >= TOT_E) return;
    int src, dst;
    if (i < N_EDGES) { src = ei[i]; dst = ei[N_EDGES + i]; }
    else             { src = dst = i - N_EDGES; }
    int pos = atomicAdd(&g_cursor[dst], 1);
    g_csrc[pos] = src;
}

// ---------------------------------------------------------------------------
// bf16 GEMM + fused attention-score epilogue.
// C[N,M](bf16) = A[N,K](bf16) * B[M,K]^T(fp32, packed to bf16)
// asrc[n,h] += sum_c C[n, h*Cc+c]*att_src[h*Cc+c]  (same for adst) via atomics.
// BM=128, BN=128, BK=32; 8 warps (4M x 2N), warp tile 32x64.
// ---------------------------------------------------------------------------
__global__ void __launch_bounds__(256, 2)
gemm_att(const __nv_bfloat16* __restrict__ A, const float* __restrict__ B,
         __nv_bfloat16* __restrict__ C,
         const float* __restrict__ att_src, const float* __restrict__ att_dst,
         float* __restrict__ asrc, float* __restrict__ adst,
         int N, int M, int K, int H, int Cc) {
    const int BM = 128, BN = 128, BK = 32, BK2 = 16;
    __shared__ uint32_t As[2][BM][BK2 + 2];
    __shared__ uint32_t Bs[2][BN][BK2 + 2];

    int tid  = threadIdx.x;
    int lane = tid & 31;
    int wid  = tid >> 5;
    int wr = (wid & 3) * 32;     // 4 warps over M
    int wc = (wid >> 2) * 64;    // 2 warps over N
    int gid = lane >> 2;
    int tig = lane & 3;

    int blockRow = blockIdx.y * BM;
    int blockCol = blockIdx.x * BN;

    // A: 128x32 bf16 = 512 uint4, 2/thr. B: 128x32 fp32 = 1024 float4, 4/thr.
    uint4  va[2];
    float4 vb[4];
    const uint4  zu4 = make_uint4(0, 0, 0, 0);
    const float4 zf4 = make_float4(0.f, 0.f, 0.f, 0.f);
    int ar[2], aq[2], br[4], bq[4];
#pragma unroll
    for (int l = 0; l < 2; l++) { int idx = tid + l * 256; ar[l] = idx >> 2; aq[l] = idx & 3; }
#pragma unroll
    for (int l = 0; l < 4; l++) { int idx = tid + l * 256; br[l] = idx >> 3; bq[l] = idx & 7; }

    auto loadTile = [&](int k0) {
#pragma unroll
        for (int l = 0; l < 2; l++)
            va[l] = (blockRow + ar[l] < N)
                  ? *(const uint4*)(A + (size_t)(blockRow + ar[l]) * K + k0 + aq[l] * 8) : zu4;
#pragma unroll
        for (int l = 0; l < 4; l++)
            vb[l] = (blockCol + br[l] < M)
                  ? *(const float4*)(B + (size_t)(blockCol + br[l]) * K + k0 + bq[l] * 4) : zf4;
    };
    auto storeTile = [&](int buf) {
#pragma unroll
        for (int l = 0; l < 2; l++) {
            As[buf][ar[l]][aq[l] * 4]     = va[l].x;
            As[buf][ar[l]][aq[l] * 4 + 1] = va[l].y;
            As[buf][ar[l]][aq[l] * 4 + 2] = va[l].z;
            As[buf][ar[l]][aq[l] * 4 + 3] = va[l].w;
        }
#pragma unroll
        for (int l = 0; l < 4; l++) {
            Bs[buf][br[l]][bq[l] * 2]     = pack_bf16x2(vb[l].x, vb[l].y);
            Bs[buf][br[l]][bq[l] * 2 + 1] = pack_bf16x2(vb[l].z, vb[l].w);
        }
    };

    float acc[2][8][4];
#pragma unroll
    for (int mt = 0; mt < 2; mt++)
#pragma unroll
        for (int nt = 0; nt < 8; nt++)
#pragma unroll
            for (int i = 0; i < 4; i++) acc[mt][nt][i] = 0.f;

    loadTile(0);
    storeTile(0);
    __syncthreads();

    int buf = 0;
    for (int k0 = BK; k0 <= K; k0 += BK) {
        bool has = (k0 < K);
        if (has) loadTile(k0);

#pragma unroll
        for (int ks = 0; ks < 2; ks++) {
            int kb = ks * 8;
            uint32_t a[2][4], b[8][2];
#pragma unroll
            for (int mt = 0; mt < 2; mt++) {
                int r0 = wr + mt * 16;
                a[mt][0] = As[buf][r0 + gid    ][kb + tig    ];
                a[mt][1] = As[buf][r0 + gid + 8][kb + tig    ];
                a[mt][2] = As[buf][r0 + gid    ][kb + tig + 4];
                a[mt][3] = As[buf][r0 + gid + 8][kb + tig + 4];
            }
#pragma unroll
            for (int nt = 0; nt < 8; nt++) {
                int n0 = wc + nt * 8 + gid;
                b[nt][0] = Bs[buf][n0][kb + tig    ];
                b[nt][1] = Bs[buf][n0][kb + tig + 4];
            }
#pragma unroll
            for (int mt = 0; mt < 2; mt++)
#pragma unroll
                for (int nt = 0; nt < 8; nt++) {
                    asm volatile(
                        "mma.sync.aligned.m16n8k16.row.col.f32.bf16.bf16.f32 "
                        "{%0,%1,%2,%3}, {%4,%5,%6,%7}, {%8,%9}, {%0,%1,%2,%3};"
                        : "+f"(acc[mt][nt][0]), "+f"(acc[mt][nt][1]),
                          "+f"(acc[mt][nt][2]), "+f"(acc[mt][nt][3])
                        : "r"(a[mt][0]), "r"(a[mt][1]), "r"(a[mt][2]), "r"(a[mt][3]),
                          "r"(b[nt][0]), "r"(b[nt][1]));
                }
        }

        if (has) storeTile(buf ^ 1);
        __syncthreads();
        buf ^= 1;
    }

    // ---- store C (bf16 pairs) + accumulate att partials ----
    int h_first = (blockCol + wc) / Cc;
    float psrc[2][2][2] = {};   // [mt][rowhalf][bucket]
    float pdst[2][2][2] = {};

#pragma unroll
    for (int mt = 0; mt < 2; mt++) {
#pragma unroll
        for (int nt = 0; nt < 8; nt++) {
            int r0 = blockRow + wr + mt * 16 + gid;
            int c0 = blockCol + wc + nt * 8 + tig * 2;
            if (c0 < M) {
                if (r0 < N)
                    *(uint32_t*)(C + (size_t)r0 * M + c0) =
                        pack_bf16x2(acc[mt][nt][0], acc[mt][nt][1]);
                if (r0 + 8 < N)
                    *(uint32_t*)(C + (size_t)(r0 + 8) * M + c0) =
                        pack_bf16x2(acc[mt][nt][2], acc[mt][nt][3]);
                int hb = (blockCol + wc + nt * 8) / Cc - h_first;   // 0 or 1
                float a0 = att_src[c0], a1 = att_src[c0 + 1];
                float d0 = att_dst[c0], d1 = att_dst[c0 + 1];
                psrc[mt][0][hb] += acc[mt][nt][0] * a0 + acc[mt][nt][1] * a1;
                psrc[mt][1][hb] += acc[mt][nt][2] * a0 + acc[mt][nt][3] * a1;
                pdst[mt][0][hb] += acc[mt][nt][0] * d0 + acc[mt][nt][1] * d1;
                pdst[mt][1][hb] += acc[mt][nt][2] * d0 + acc[mt][nt][3] * d1;
            }
        }
    }
    // quad-reduce over tig (lanes gid*4 + tig)
#pragma unroll
    for (int mt = 0; mt < 2; mt++)
#pragma unroll
        for (int hf = 0; hf < 2; hf++)
#pragma unroll
            for (int bk = 0; bk < 2; bk++) {
                float s = psrc[mt][hf][bk], d = pdst[mt][hf][bk];
                s += __shfl_xor_sync(0xffffffffu, s, 1);
                s += __shfl_xor_sync(0xffffffffu, s, 2);
                d += __shfl_xor_sync(0xffffffffu, d, 1);
                d += __shfl_xor_sync(0xffffffffu, d, 2);
                psrc[mt][hf][bk] = s; pdst[mt][hf][bk] = d;
            }
    if (tig == 0) {
#pragma unroll
        for (int mt = 0; mt < 2; mt++)
#pragma unroll
            for (int hf = 0; hf < 2; hf++) {
                int row = blockRow + wr + mt * 16 + gid + hf * 8;
                if (row >= N) continue;
#pragma unroll
                for (int bk = 0; bk < 2; bk++) {
                    int hidx = h_first + bk;
                    if (hidx < H) {
                        atomicAdd(&asrc[row * H + hidx], psrc[mt][hf][bk]);
                        atomicAdd(&adst[row * H + hidx], pdst[mt][hf][bk]);
                    }
                }
            }
    }
}

// ---------------------------------------------------------------------------
// GAT aggregation, H=5. One block (192 thr) per node. Single-pass e into smem.
// ---------------------------------------------------------------------------
template<int C>
__global__ void __launch_bounds__(192)
gat_agg5(const __nv_bfloat16* __restrict__ hfeat,
         const float* __restrict__ asrc,
         const float* __restrict__ adst,
         const float* __restrict__ bias,
         __nv_bfloat16* __restrict__ out) {
    const int HC = 5 * C, NC4 = HC / 4;
    const int EMAX = 128;
    __shared__ float s_e[EMAX * 5];
    __shared__ int   s_src[EMAX];
    __shared__ float s_m[5], s_iz[5], s_ad[5];

    int v = blockIdx.x;
    int tid = threadIdx.x, lane = tid & 31, wid = tid >> 5;
    int base = g_rowptr[v];
    int deg = g_rowptr[v + 1] - base;

    if (tid < 5) s_ad[tid] = adst[v * 5 + tid];
    __syncthreads();

    float4 acc = make_float4(0.f, 0.f, 0.f, 0.f);
    int head = (tid * 4) / C;

    if (deg <= EMAX) {
        // one pass: gather asrc, compute leaky e into smem
        for (int idx = tid; idx < deg * 5; idx += 192) {
            int j = idx / 5, hh = idx - j * 5;
            int s = g_csrc[base + j];
            if (hh == 0) s_src[j] = s;
            float e = asrc[s * 5 + hh] + s_ad[hh];
            s_e[idx] = (e > 0.f) ? e : NEG_SLOPE * e;
        }
        __syncthreads();
        // per-head max and Z from smem; overwrite s_e with exp(e-m)
        if (wid < 5) {
            int h = wid;
            float m = -INFINITY;
            for (int j = lane; j < deg; j += 32)
                m = fmaxf(m, s_e[j * 5 + h]);
#pragma unroll
            for (int o = 16; o > 0; o >>= 1)
                m = fmaxf(m, __shfl_xor_sync(0xffffffffu, m, o));
            float z = 0.f;
            for (int j = lane; j < deg; j += 32) {
                float ex = __expf(s_e[j * 5 + h] - m);
                s_e[j * 5 + h] = ex;
                z += ex;
            }
#pragma unroll
            for (int o = 16; o > 0; o >>= 1)
                z += __shfl_xor_sync(0xffffffffu, z, o);
            if (lane == 0) s_iz[h] = 1.f / (z + EPS_F);
        }
        __syncthreads();
        // normalize
        for (int idx = tid; idx < deg * 5; idx += 192) {
            int hh = idx % 5;
            s_e[idx] *= s_iz[hh];
        }
        __syncthreads();
        // gather features
        if (tid < NC4) {
#pragma unroll 2
            for (int j = 0; j < deg; j++) {
                const uint2* hp = (const uint2*)(hfeat + (size_t)s_src[j] * HC);
                float w = s_e[j * 5 + head];
                uint2 hv = hp[tid];
                float2 lo = __bfloat1622float2(*(__nv_bfloat162*)&hv.x);
                float2 hi = __bfloat1622float2(*(__nv_bfloat162*)&hv.y);
                acc.x += w * lo.x; acc.y += w * lo.y;
                acc.z += w * hi.x; acc.w += w * hi.y;
            }
        }
    } else {
        // fallback (deg > EMAX): 3-phase with global reads
        if (wid < 5) {
            int h = wid;
            float ad = s_ad[h];
            float m = -INFINITY;
            for (int j = lane; j < deg; j += 32) {
                int s = g_csrc[base + j];
                float e = asrc[s * 5 + h] + ad;
                e = (e > 0.f) ? e : NEG_SLOPE * e;
                m = fmaxf(m, e);
            }
#pragma unroll
            for (int o = 16; o > 0; o >>= 1)
                m = fmaxf(m, __shfl_xor_sync(0xffffffffu, m, o));
            float z = 0.f;
            for (int j = lane; j < deg; j += 32) {
                int s = g_csrc[base + j];
                float e = asrc[s * 5 + h] + ad;
                e = (e > 0.f) ? e : NEG_SLOPE * e;
                z += __expf(e - m);
            }
#pragma unroll
            for (int o = 16; o > 0; o >>= 1)
                z += __shfl_xor_sync(0xffffffffu, z, o);
            if (lane == 0) { s_m[h] = m; s_iz[h] = 1.f / (z + EPS_F); }
        }
        __syncthreads();
        for (int j0 = 0; j0 < deg; j0 += EMAX) {
            int ch = min(EMAX, deg - j0);
            for (int idx = tid; idx < ch * 5; idx += 192) {
                int j = idx / 5, hh = idx - j * 5;
                int s = g_csrc[base + j0 + j];
                if (hh == 0) s_src[j] = s;
                float e = asrc[s * 5 + hh] + s_ad[hh];
                e = (e > 0.f) ? e : NEG_SLOPE * e;
                s_e[j * 5 + hh] = __expf(e - s_m[hh]) * s_iz[hh];
            }
            __syncthreads();
            if (tid < NC4) {
                for (int j = 0; j < ch; j++) {
                    const uint2* hp = (const uint2*)(hfeat + (size_t)s_src[j] * HC);
                    float w = s_e[j * 5 + head];
                    uint2 hv = hp[tid];
                    float2 lo = __bfloat1622float2(*(__nv_bfloat162*)&hv.x);
                    float2 hi = __bfloat1622float2(*(__nv_bfloat162*)&hv.y);
                    acc.x += w * lo.x; acc.y += w * lo.y;
                    acc.z += w * hi.x; acc.w += w * hi.y;
                }
            }
            __syncthreads();
        }
    }

    if (tid < NC4) {
        float4 b = ((const float4*)bias)[tid];
        uint2 o;
        o.x = pack_bf16x2(fmaxf(acc.x + b.x, 0.f), fmaxf(acc.y + b.y, 0.f));
        o.y = pack_bf16x2(fmaxf(acc.z + b.z, 0.f), fmaxf(acc.w + b.w, 0.f));
        ((uint2*)(out + (size_t)v * HC))[tid] = o;
    }
}

// ---------------------------------------------------------------------------
// GAT aggregation, H=1, C=32 + fused global_add_pool. warp per node.
// ---------------------------------------------------------------------------
__global__ void __launch_bounds__(256)
gat_agg1_pool(const __nv_bfloat16* __restrict__ hfeat,
              const float* __restrict__ asrc,
              const float* __restrict__ adst,
              const float* __restrict__ bias,
              const int* __restrict__ batch) {
    int wid = threadIdx.x >> 5, lane = threadIdx.x & 31;
    int v = blockIdx.x * 8 + wid;
    if (v >= N_NODES) return;
    int base = g_rowptr[v];
    int deg = g_rowptr[v + 1] - base;
    float ad = adst[v];

    float m = -INFINITY;
    for (int j = lane; j < deg; j += 32) {
        int s = g_csrc[base + j];
        float e = asrc[s] + ad;
        e = (e > 0.f) ? e : NEG_SLOPE * e;
        m = fmaxf(m, e);
    }
#pragma unroll
    for (int o = 16; o > 0; o >>= 1)
        m = fmaxf(m, __shfl_xor_sync(0xffffffffu, m, o));
    float z = 0.f;
    for (int j = lane; j < deg; j += 32) {
        int s = g_csrc[base + j];
        float e = asrc[s] + ad;
        e = (e > 0.f) ? e : NEG_SLOPE * e;
        z += __expf(e - m);
    }
#pragma unroll
    for (int o = 16; o > 0; o >>= 1)
        z += __shfl_xor_sync(0xffffffffu, z, o);
    float iz = 1.f / (z + EPS_F);

    float acc = 0.f;
#pragma unroll 2
    for (int j = 0; j < deg; j++) {
        int s = g_csrc[base + j];
        float e = asrc[s] + ad;
        e = (e > 0.f) ? e : NEG_SLOPE * e;
        float w = __expf(e - m) * iz;
        acc += w * __bfloat162float(hfeat[(size_t)s * 32 + lane]);
    }
    float o = fmaxf(acc + bias[lane], 0.f);
    atomicAdd(&g_pool[batch[v] * 32 + lane], o);
}

// ---------------------------------------------------------------------------
// MLP head
// ---------------------------------------------------------------------------
__global__ void mlp_kernel(const float* __restrict__ lin_w,
                           const float* __restrict__ lin_b,
                           const float* __restrict__ lin2_w,
                           const float* __restrict__ lin2_b,
                           float* __restrict__ out) {
    int g = blockIdx.x;
    __shared__ float sg[32];
    __shared__ float sred[256];
    int tid = threadIdx.x;
    if (tid < 32) sg[tid] = g_pool[g * 32 + tid];
    __syncthreads();
    float partial = 0.f;
    for (int u = tid; u < 1024; u += 256) {
        float d = lin_b[u];
        const float* wr = lin_w + u * 32;
#pragma unroll
        for (int c = 0; c < 32; c++) d += sg[c] * wr[c];
        d = fmaxf(d, 0.f);
        partial += d * lin2_w[u];
    }
    sred[tid] = partial;
    __syncthreads();
    for (int s = 128; s > 0; s >>= 1) {
        if (tid < s) sred[tid] += sred[tid + s];
        __syncthreads();
    }
    if (tid == 0) {
        float v = sred[0] + lin2_b[0];
        out[g] = 1.f / (1.f + __expf(-v));
    }
}

// ---------------------------------------------------------------------------
// launch
// ---------------------------------------------------------------------------
extern "C" void kernel_launch(void* const* d_in, const int* in_sizes, int n_in,
                              void* d_out, int out_size) {
    const float* x        = (const float*)d_in[0];
    const float* W1       = (const float*)d_in[1];
    const float* att_s1   = (const float*)d_in[2];
    const float* att_d1   = (const float*)d_in[3];
    const float* b1       = (const float*)d_in[4];
    const float* W2       = (const float*)d_in[5];
    const float* att_s2   = (const float*)d_in[6];
    const float* att_d2   = (const float*)d_in[7];
    const float* b2       = (const float*)d_in[8];
    const float* W3       = (const float*)d_in[9];
    const float* att_s3   = (const float*)d_in[10];
    const float* att_d3   = (const float*)d_in[11];
    const float* b3       = (const float*)d_in[12];
    const float* lin_w    = (const float*)d_in[13];
    const float* lin_b    = (const float*)d_in[14];
    const float* lin2_w   = (const float*)d_in[15];
    const float* lin2_b   = (const float*)d_in[16];
    const int*   ei       = (const int*)d_in[17];
    const int*   batch    = (const int*)d_in[18];
    float* out = (float*)d_out;

    __nv_bfloat16 *xq, *h1, *o1, *h2, *o2, *h3;
    float *attbuf, *pool;
    int *cnt;
    cudaGetSymbolAddress((void**)&xq, g_xq);
    cudaGetSymbolAddress((void**)&h1, g_h1);
    cudaGetSymbolAddress((void**)&o1, g_o1);
    cudaGetSymbolAddress((void**)&h2, g_h2);
    cudaGetSymbolAddress((void**)&o2, g_o2);
    cudaGetSymbolAddress((void**)&h3, g_h3);
    cudaGetSymbolAddress((void**)&attbuf, g_att);
    cudaGetSymbolAddress((void**)&pool, g_pool);
    cudaGetSymbolAddress((void**)&cnt, g_cnt);

    float* as1 = attbuf;                    float* ad1 = attbuf + N_NODES * 5;
    float* as2 = attbuf + 2 * N_NODES * 5;  float* ad2 = attbuf + 3 * N_NODES * 5;
    float* as3 = attbuf + 4 * N_NODES * 5;  float* ad3 = attbuf + 5 * N_NODES * 5;

    static cudaStream_t s_cs = nullptr;
    static cudaEvent_t ev_fork = nullptr, ev_join = nullptr;
    if (!s_cs) {
        cudaStreamCreateWithFlags(&s_cs, cudaStreamNonBlocking);
        cudaEventCreateWithFlags(&ev_fork, cudaEventDisableTiming);
        cudaEventCreateWithFlags(&ev_join, cudaEventDisableTiming);
    }

    // ---- fork: CSR build + pool zero on side stream ----
    cudaEventRecord(ev_fork, 0);
    cudaStreamWaitEvent(s_cs, ev_fork, 0);
    cudaMemsetAsync(cnt, 0, N_NODES * sizeof(int), s_cs);
    cudaMemsetAsync(pool, 0, N_GRAPHS * 32 * sizeof(float), s_cs);
    count_kernel<<<(N_EDGES + 255) / 256, 256, 0, s_cs>>>(ei);
    scan1_kernel<<<N_BLK, 256, 0, s_cs>>>();
    scan3_kernel<<<N_BLK, 256, 0, s_cs>>>();
    scatter_kernel<<<(TOT_E + 255) / 256, 256, 0, s_cs>>>(ei);
    cudaEventRecord(ev_join, s_cs);

    // ---- main: zero att accumulators, convert x, GEMM1 (att fused) ----
    cudaMemsetAsync(attbuf, 0, 6 * N_NODES * 5 * sizeof(float), 0);
    convert_x<<<(N_NODES * 64 / 4 + 255) / 256, 256>>>(x);

    const int GY = (N_NODES + 127) / 128;

    {
        dim3 grid((HC1 + 127) / 128, GY);
        gemm_att<<<grid, 256>>>(xq, W1, h1, att_s1, att_d1, as1, ad1,
                                N_NODES, HC1, 64, 5, 64);
    }

    // ---- join: aggregation needs CSR ----
    cudaStreamWaitEvent(0, ev_join, 0);
    gat_agg5<64><<<N_NODES, 192>>>(h1, as1, ad1, b1, o1);

    // ---- Layer 2 ----
    {
        dim3 grid((HC2 + 127) / 128, GY);
        gemm_att<<<grid, 256>>>(o1, W2, h2, att_s2, att_d2, as2, ad2,
                                N_NODES, HC2, HC1, 5, 96);
        gat_agg5<96><<<N_NODES, 192>>>(h2, as2, ad2, b2, o2);
    }
    // ---- Layer 3 (agg fused with pool) ----
    {
        dim3 grid((HC3 + 127) / 128, GY);
        gemm_att<<<grid, 256>>>(o2, W3, h3, att_s3, att_d3, as3, ad3,
                                N_NODES, HC3, HC2, 1, 32);
        gat_agg1_pool<<<(N_NODES + 7) / 8, 256>>>(h3, as3, ad3, b3, batch);
    }

    // ---- MLP head ----
    mlp_kernel<<<N_GRAPHS, 256>>>(lin_w, lin_b, lin2_w, lin2_b, out);
}